// round 13
// baseline (speedup 1.0000x reference)
#include <cuda_runtime.h>
#include <cuda_bf16.h>
#include <cstdint>
#include <cstddef>

// Problem constants
#define BATCH   64
#define SEQ     2048
#define IDIM    256
#define HDIM    512
#define BDIM    256
#define INDIM   1280     // 3*IDIM + HDIM
#define XPART   768      // 3*IDIM
#define M_TOTAL (BATCH * SEQ)   // 131072
#define NG      1536     // 3 gates * HDIM

#define NBLK2   64       // persistent recurrent grid: 64 CTAs x 2 batch-slabs each

// -------------------- scratch (static __device__, allocation-free) --------------------
__device__ float g_XG[(size_t)M_TOTAL * NG];        // [b*SEQ+t][1536]: xz | xr | xh pre-acts
__device__ unsigned g_bar2[8 * 64];                 // per-slab: hcnt @ s*64, rhcnt @ s*64+32

// packed bf16 hi|lo exchange buffers (u32 = hi | lo<<16)
__device__ unsigned g_hpk [BATCH * HDIM];           // h_t
__device__ unsigned g_rhpk[BATCH * HDIM];           // r*h

// bf16 split operands
__device__ __nv_bfloat16 g_Xh[(size_t)M_TOTAL * XPART];   // x concat hi, [b*SEQ+t][768]
__device__ __nv_bfloat16 g_Xl[(size_t)M_TOTAL * XPART];
__device__ __nv_bfloat16 g_Wxh[(size_t)NG * XPART];       // [1536][768] x-part of Wz|Wr|Wh
__device__ __nv_bfloat16 g_Wxl[(size_t)NG * XPART];
__device__ __nv_bfloat16 g_Hh[(size_t)M_TOTAL * HDIM];    // hidden states, [b*SEQ+t][512]
__device__ __nv_bfloat16 g_Hl[(size_t)M_TOTAL * HDIM];
__device__ __nv_bfloat16 g_Wbh[(size_t)BDIM * HDIM];
__device__ __nv_bfloat16 g_Wbl[(size_t)BDIM * HDIM];
__device__ float g_bcat[NG];

// =====================================================================================
// MMA / ldmatrix / cp.async macros (portable sm_80+ PTX)
// =====================================================================================
#define LDM_X4(r0, r1, r2, r3, a) \
    asm volatile("ldmatrix.sync.aligned.m8n8.x4.shared.b16 {%0,%1,%2,%3}, [%4];" \
                 : "=r"(r0), "=r"(r1), "=r"(r2), "=r"(r3) : "r"(a))
#define LDM_X2(r0, r1, a) \
    asm volatile("ldmatrix.sync.aligned.m8n8.x2.shared.b16 {%0,%1}, [%2];" \
                 : "=r"(r0), "=r"(r1) : "r"(a))
#define MMA16816(d, a, b) \
    asm volatile("mma.sync.aligned.m16n8k16.row.col.f32.bf16.bf16.f32 " \
                 "{%0,%1,%2,%3}, {%4,%5,%6,%7}, {%8,%9}, {%0,%1,%2,%3};" \
                 : "+f"((d)[0]), "+f"((d)[1]), "+f"((d)[2]), "+f"((d)[3]) \
                 : "r"((a)[0]), "r"((a)[1]), "r"((a)[2]), "r"((a)[3]), \
                   "r"((b)[0]), "r"((b)[1]))
#define CP_ASYNC16(dst, src) \
    asm volatile("cp.async.cg.shared.global [%0], [%1], 16;" :: "r"(dst), "l"(src))
#define CP_COMMIT() asm volatile("cp.async.commit_group;" ::: "memory")
#define CP_WAIT1()  asm volatile("cp.async.wait_group 1;" ::: "memory")
#define CP_WAIT0()  asm volatile("cp.async.wait_group 0;" ::: "memory")

__device__ __forceinline__ uint32_t smem_u32(const void* p) {
    uint32_t a;
    asm("{ .reg .u64 t; cvta.to.shared.u64 t, %1; cvt.u32.u64 %0, t; }" : "=r"(a) : "l"(p));
    return a;
}

// =====================================================================================
// Prep kernels: build bf16 hi/lo split operands
// =====================================================================================
__global__ void __launch_bounds__(256) prep_wx_kernel(
    const float* __restrict__ Wz, const float* __restrict__ Wr, const float* __restrict__ Wh,
    const float* __restrict__ bz, const float* __restrict__ br, const float* __restrict__ bh)
{
    int idx = blockIdx.x * 256 + threadIdx.x;
    if (idx < NG * XPART) {
        int j = idx / XPART, k = idx - j * XPART;
        int gate = j >> 9, jj = j & 511;
        const float* W = (gate == 0) ? Wz : (gate == 1) ? Wr : Wh;
        float v = W[(size_t)jj * INDIM + k];
        __nv_bfloat16 hi = __float2bfloat16(v);
        __nv_bfloat16 lo = __float2bfloat16(v - __bfloat162float(hi));
        g_Wxh[idx] = hi; g_Wxl[idx] = lo;
    }
    if (idx < NG) {
        g_bcat[idx] = (idx < 512) ? bz[idx] : (idx < 1024) ? br[idx - 512] : bh[idx - 1024];
    }
}

__global__ void __launch_bounds__(256) prep_wb_kernel(const float* __restrict__ Wb)
{
    int idx = blockIdx.x * 256 + threadIdx.x;
    if (idx < BDIM * HDIM) {
        float v = Wb[idx];
        __nv_bfloat16 hi = __float2bfloat16(v);
        __nv_bfloat16 lo = __float2bfloat16(v - __bfloat162float(hi));
        g_Wbh[idx] = hi; g_Wbl[idx] = lo;
    }
}

// x (b, s, t, i) -> Xh/Xl[(b*SEQ+t)*768 + s*256 + i]
__global__ void __launch_bounds__(256) prep_x_kernel(const float* __restrict__ x)
{
    int idx = blockIdx.x * 256 + threadIdx.x;      // one float4
    size_t e = (size_t)idx * 4;
    int b = (int)(e / 1572864);                    // 3*2048*256
    int r = (int)(e - (size_t)b * 1572864);
    int s = r / 524288;                            // 2048*256
    int r2 = r - s * 524288;
    int t = r2 >> 8, i = r2 & 255;
    float4 v = *(const float4*)(x + e);
    size_t dst = ((size_t)b * SEQ + t) * XPART + s * 256 + i;
    __nv_bfloat16 hx = __float2bfloat16(v.x), hy = __float2bfloat16(v.y);
    __nv_bfloat16 hz = __float2bfloat16(v.z), hw = __float2bfloat16(v.w);
    *(__nv_bfloat162*)(g_Xh + dst)     = __nv_bfloat162(hx, hy);
    *(__nv_bfloat162*)(g_Xh + dst + 2) = __nv_bfloat162(hz, hw);
    *(__nv_bfloat162*)(g_Xl + dst)     = __nv_bfloat162(
        __float2bfloat16(v.x - __bfloat162float(hx)), __float2bfloat16(v.y - __bfloat162float(hy)));
    *(__nv_bfloat162*)(g_Xl + dst + 2) = __nv_bfloat162(
        __float2bfloat16(v.z - __bfloat162float(hz)), __float2bfloat16(v.w - __bfloat162float(hw)));
}

// =====================================================================================
// cp.async double-buffered SUPER-CHUNK mma.sync GEMM (stages 1 & 3) — round-10 version.
// =====================================================================================
#define GSTRIDE 80                      // smem row stride bytes (32 bf16 data + 8 pad)
#define G_TILE  (128 * GSTRIDE)         // 10240
#define G_STAGE (4 * G_TILE)            // 40960: Ah | Al | Bh | Bl
#define GEMM_SMEM (2 * G_STAGE)         // 81920

__global__ void __launch_bounds__(256, 2) gemm_mma_kernel(
    const __nv_bfloat16* __restrict__ Ah, const __nv_bfloat16* __restrict__ Al, int lda,
    const __nv_bfloat16* __restrict__ Bh, const __nv_bfloat16* __restrict__ Bl, int ldb,
    const float* __restrict__ bias, float* __restrict__ C, int ldc, int K32)
{
    extern __shared__ char gsm[];
    const uint32_t sbase = smem_u32(gsm);

    const int tid  = threadIdx.x;
    const int wid  = tid >> 5;
    const int lane = tid & 31;
    const int n0   = blockIdx.x * 128;
    const int m0   = blockIdx.y * 128;
    const int m0w  = (wid & 1) * 64;
    const int n0w  = (wid >> 1) * 32;

    const int NC = K32;                 // super-chunks

    const uint32_t a_base = (uint32_t)(((lane & 7) + ((lane >> 3) & 1) * 8) * GSTRIDE
                                       + ((lane >> 4) & 1) * 16);
    const uint32_t b_base = (uint32_t)(((lane & 7) + ((lane >> 4) & 1) * 8) * GSTRIDE
                                       + ((lane >> 3) & 1) * 16);

    float acc[4][4][4];
    #pragma unroll
    for (int i = 0; i < 4; i++)
        #pragma unroll
        for (int j = 0; j < 4; j++)
            #pragma unroll
            for (int q = 0; q < 4; q++) acc[i][j][q] = 0.f;

    auto issue = [&](int c) {
        const int kk = c * 32;
        const uint32_t sb = sbase + (uint32_t)((c & 1) * G_STAGE);
        const int u = tid, row = u >> 2, c16 = u & 3;
        #pragma unroll
        for (int i = 0; i < 2; i++) {
            int rr = row + i * 64;
            uint32_t so = (uint32_t)(rr * GSTRIDE + c16 * 16);
            size_t goA = (size_t)(m0 + rr) * lda + kk + c16 * 8;
            size_t goB = (size_t)(n0 + rr) * ldb + kk + c16 * 8;
            CP_ASYNC16(sb + so,              Ah + goA);
            CP_ASYNC16(sb + G_TILE + so,     Al + goA);
            CP_ASYNC16(sb + 2*G_TILE + so,   Bh + goB);
            CP_ASYNC16(sb + 3*G_TILE + so,   Bl + goB);
        }
        CP_COMMIT();
    };

    issue(0);

    #pragma unroll 1
    for (int c = 0; c < NC; c++) {
        if (c + 1 < NC) { issue(c + 1); CP_WAIT1(); } else { CP_WAIT0(); }
        __syncthreads();

        const uint32_t sb  = sbase + (uint32_t)((c & 1) * G_STAGE);
        const uint32_t sAh = sb + (uint32_t)(m0w * GSTRIDE) + a_base;
        const uint32_t sAl = sAh + G_TILE;
        const uint32_t sBh = sb + 2*G_TILE + (uint32_t)(n0w * GSTRIDE) + b_base;
        const uint32_t sBl = sBh + G_TILE;

        #pragma unroll
        for (int ks = 0; ks < 2; ks++) {
            const uint32_t ko = (uint32_t)(ks * 32);
            uint32_t ahf[4][4], bhf[4][2];
            #pragma unroll
            for (int mb = 0; mb < 4; mb++)
                LDM_X4(ahf[mb][0], ahf[mb][1], ahf[mb][2], ahf[mb][3],
                       sAh + (uint32_t)(mb * 16 * GSTRIDE) + ko);
            #pragma unroll
            for (int q = 0; q < 2; q++)
                LDM_X4(bhf[2*q][0], bhf[2*q][1], bhf[2*q+1][0], bhf[2*q+1][1],
                       sBh + (uint32_t)(q * 16 * GSTRIDE) + ko);
            #pragma unroll
            for (int mb = 0; mb < 4; mb++)
                #pragma unroll
                for (int nb = 0; nb < 4; nb++)
                    MMA16816(acc[mb][nb], ahf[mb], bhf[nb]);     // Ah*Bh

            uint32_t alf[4][4];
            #pragma unroll
            for (int mb = 0; mb < 4; mb++)
                LDM_X4(alf[mb][0], alf[mb][1], alf[mb][2], alf[mb][3],
                       sAl + (uint32_t)(mb * 16 * GSTRIDE) + ko);
            #pragma unroll
            for (int mb = 0; mb < 4; mb++)
                #pragma unroll
                for (int nb = 0; nb < 4; nb++)
                    MMA16816(acc[mb][nb], alf[mb], bhf[nb]);     // Al*Bh

            uint32_t blf[4][2];
            #pragma unroll
            for (int q = 0; q < 2; q++)
                LDM_X4(blf[2*q][0], blf[2*q][1], blf[2*q+1][0], blf[2*q+1][1],
                       sBl + (uint32_t)(q * 16 * GSTRIDE) + ko);
            #pragma unroll
            for (int mb = 0; mb < 4; mb++)
                #pragma unroll
                for (int nb = 0; nb < 4; nb++)
                    MMA16816(acc[mb][nb], ahf[mb], blf[nb]);     // Ah*Bl
        }
        __syncthreads();
    }

    const int g   = lane >> 2;
    const int tig = lane & 3;
    #pragma unroll
    for (int mb = 0; mb < 4; mb++) {
        #pragma unroll
        for (int nb = 0; nb < 4; nb++) {
            int col = n0 + n0w + nb * 8 + tig * 2;
            float b0 = bias[col], b1 = bias[col + 1];
            int r0 = m0 + m0w + mb * 16 + g;
            *(float2*)(C + (size_t)r0 * ldc + col) =
                make_float2(acc[mb][nb][0] + b0, acc[mb][nb][1] + b1);
            *(float2*)(C + (size_t)(r0 + 8) * ldc + col) =
                make_float2(acc[mb][nb][2] + b0, acc[mb][nb][3] + b1);
        }
    }
}

// =====================================================================================
// Stage 2: persistent TENSOR-CORE recurrence — DUAL-SLAB INTERLEAVE.
//   64 CTAs: CTA (pair = blk>>4 in 0..3, jrank = blk&15) handles batch-slabs
//   s0 = pair and s1 = pair+4 with the SAME j-slab (weights shared in smem).
//   Barrier split into arrive (red.release in combine) + wait (thread-0 poll);
//   every wait is preceded by the other slab's compute, hiding barrier+exchange
//   latency. Sync/exchange primitives are round-10's proven ones.
// =====================================================================================
#define WROW   1040                 // weight/A smem row stride in bytes (520 bf16)
#define OFF_WZRH 0
#define OFF_WZRL (OFF_WZRH + 64*WROW)
#define OFF_WHH  (OFF_WZRL + 64*WROW)
#define OFF_WHL  (OFF_WHH  + 32*WROW)
#define OFF_AHI  (OFF_WHL  + 32*WROW)
#define OFF_ALO  (OFF_AHI  + 8*WROW)
#define OFF_CRED (OFF_ALO  + 8*WROW)
#define OFF_H32  (OFF_CRED + 2*8*66*4)      // [2][256] fp32
#define OFF_ZB   (OFF_H32  + 2048)          // [2][256] fp32
#define SMEM2_TOTAL (OFF_ZB + 2048)

#define CRED(p, h, r, n) p[((h) * 8 + (r)) * 66 + (n)]

__device__ __forceinline__ void bar_arrive(unsigned* cnt) {
    __syncthreads();                 // all threads' prior global stores done
    if (threadIdx.x == 0)
        asm volatile("red.release.gpu.global.add.u32 [%0], %1;" :: "l"(cnt), "r"(1u));
}
__device__ __forceinline__ void bar_wait(unsigned* cnt, unsigned target) {
    if (threadIdx.x == 0) {
        unsigned c;
        do {
            asm volatile("ld.acquire.gpu.global.u32 %0, [%1];" : "=r"(c) : "l"(cnt));
        } while ((int)(c - target) < 0);
    }
    __syncthreads();
}

__global__ void __launch_bounds__(256, 1) recurrent_tc_kernel(
    const float* __restrict__ Wz, const float* __restrict__ Wr, const float* __restrict__ Wh,
    float* __restrict__ out)
{
    extern __shared__ char smem[];
    const uint32_t sbase = smem_u32(smem);
    float* credf = (float*)(smem + OFF_CRED);
    float* h32   = (float*)(smem + OFF_H32);   // [2][256]
    float* zbuf  = (float*)(smem + OFF_ZB);    // [2][256]

    const int tid  = threadIdx.x;
    const int wid  = tid >> 5;
    const int lane = tid & 31;
    const int blk  = blockIdx.x;
    const int pair = blk >> 4;                 // 0..3
    const int j0   = (blk & 15) * 32;

    const int sA_[2] = { pair, pair + 4 };
    const int b0s[2] = { pair * 8, (pair + 4) * 8 };

    // ---- load + split weights into smem (one-time) ----
    for (int e = tid; e < 64 * 512; e += 256) {
        int row = e >> 9, k = e & 511;
        const float* W = (row < 32) ? Wz : Wr;
        float v = W[(size_t)(j0 + (row & 31)) * INDIM + XPART + k];
        __nv_bfloat16 hi = __float2bfloat16(v);
        __nv_bfloat16 lo = __float2bfloat16(v - __bfloat162float(hi));
        *(__nv_bfloat16*)(smem + OFF_WZRH + row * WROW + k * 2) = hi;
        *(__nv_bfloat16*)(smem + OFF_WZRL + row * WROW + k * 2) = lo;
    }
    for (int e = tid; e < 32 * 512; e += 256) {
        int row = e >> 9, k = e & 511;
        float v = Wh[(size_t)(j0 + row) * INDIM + XPART + k];
        __nv_bfloat16 hi = __float2bfloat16(v);
        __nv_bfloat16 lo = __float2bfloat16(v - __bfloat162float(hi));
        *(__nv_bfloat16*)(smem + OFF_WHH + row * WROW + k * 2) = hi;
        *(__nv_bfloat16*)(smem + OFF_WHL + row * WROW + k * 2) = lo;
    }
    h32[tid] = 0.f;
    h32[256 + tid] = 0.f;
    // zero my exchange slices for both slabs (initial h = 0)
    g_hpk[(b0s[0] + (tid >> 5)) * HDIM + j0 + (tid & 31)] = 0u;
    g_hpk[(b0s[1] + (tid >> 5)) * HDIM + j0 + (tid & 31)] = 0u;

    // initial arrivals: h(0) published for both slabs
    bar_arrive(&g_bar2[sA_[0] * 64]);
    if (tid == 0)
        asm volatile("red.release.gpu.global.add.u32 [%0], %1;"
                     :: "l"(&g_bar2[sA_[1] * 64]), "r"(1u));

    // ---- per-warp fragment address bases (shared A tile + shared weights) ----
    const int kh  = wid >> 2;                // K half
    const int khB = kh * 512;
    const int arow  = lane & 7;
    const int isLo  = (lane >> 3) & 1;
    const uint32_t akof = (uint32_t)(((lane >> 4) & 1) * 16);
    const uint32_t aA = sbase + (isLo ? OFF_ALO : OFF_AHI) + arow * WROW + akof + khB;

    const int nsA = wid & 3;
    const int browA = nsA * 16 + (lane & 7) + ((lane >> 4) & 1) * 8;
    const uint32_t bkofA = (uint32_t)(((lane >> 3) & 1) * 16);
    const uint32_t bZH = sbase + OFF_WZRH + browA * WROW + bkofA + khB;
    const uint32_t bZL = sbase + OFF_WZRL + browA * WROW + bkofA + khB;

    const int browB = (wid & 3) * 8 + (lane & 7);
    const uint32_t bkofB = (uint32_t)(((lane >> 3) & 1) * 16);
    const uint32_t bWH = sbase + OFF_WHH + browB * WROW + bkofB + khB;
    const uint32_t bWL = sbase + OFF_WHL + browB * WROW + bkofB + khB;

    // combine mappings + running XG pointers (per slab)
    const int cbA = tid >> 6;
    const int cnA = tid & 63;
    const int colA = (cnA < 32) ? (j0 + cnA) : (512 + j0 + (cnA - 32));
    const int cbB = tid >> 5, cjB = tid & 31;
    const float* pxA0[2]; const float* pxA1[2]; const float* pxB[2];
    #pragma unroll
    for (int sl = 0; sl < 2; sl++) {
        pxA0[sl] = g_XG + (size_t)(b0s[sl] + cbA)     * SEQ * NG + colA;
        pxA1[sl] = g_XG + (size_t)(b0s[sl] + cbA + 4) * SEQ * NG + colA;
        pxB[sl]  = g_XG + (size_t)(b0s[sl] + cbB) * SEQ * NG + 1024 + j0 + cjB;
    }

    const int crow = lane >> 2;
    const int ccol = (lane & 3) * 2;

    unsigned* hpk_s [2] = { g_hpk  + (size_t)b0s[0] * HDIM, g_hpk  + (size_t)b0s[1] * HDIM };
    unsigned* rhpk_s[2] = { g_rhpk + (size_t)b0s[0] * HDIM, g_rhpk + (size_t)b0s[1] * HDIM };
    unsigned* hcnt [2] = { &g_bar2[sA_[0] * 64],      &g_bar2[sA_[1] * 64] };
    unsigned* rhcnt[2] = { &g_bar2[sA_[0] * 64 + 32], &g_bar2[sA_[1] * 64 + 32] };

    unsigned tgt = 16;    // both counters advance by 16 per step, in lockstep

    #pragma unroll 1
    for (int t = 0; t < SEQ; t++) {
        // =========== phase A for both slabs ===========
        #pragma unroll 1
        for (int sl = 0; sl < 2; sl++) {
            float xa0 = *pxA0[sl], xa1 = *pxA1[sl];
            pxA0[sl] += NG; pxA1[sl] += NG;

            bar_wait(hcnt[sl], tgt);          // h(t) of this slab visible
            // load h (packed) -> Ahi/Alo
            #pragma unroll
            for (int q = 0; q < 8; q++) {
                uint2 w = *(const uint2*)(hpk_s[sl] + q * 512 + tid * 2);
                *(uint32_t*)(smem + OFF_AHI + q * WROW + tid * 4) = __byte_perm(w.x, w.y, 0x5410);
                *(uint32_t*)(smem + OFF_ALO + q * WROW + tid * 4) = __byte_perm(w.x, w.y, 0x7632);
            }
            __syncthreads();

            // phase A mma: z|r preacts, N64
            {
                float acc0[4] = {0.f, 0.f, 0.f, 0.f};
                float acc1[4] = {0.f, 0.f, 0.f, 0.f};
                #pragma unroll
                for (int k16 = 0; k16 < 16; k16++) {
                    uint32_t off = (uint32_t)(k16 * 32);
                    uint32_t a[4], bh[4], bl[4];
                    LDM_X4(a[0], a[1], a[2], a[3], aA + off);
                    LDM_X4(bh[0], bh[1], bh[2], bh[3], bZH + off);
                    LDM_X4(bl[0], bl[1], bl[2], bl[3], bZL + off);
                    MMA16816(acc0, a, bh);
                    MMA16816(acc1, a, bh + 2);
                    MMA16816(acc0, a, bl);
                    MMA16816(acc1, a, bl + 2);
                }
                int n0w = nsA * 16;
                *(float2*)&CRED(credf, kh, crow, n0w + ccol) =
                    make_float2(acc0[0] + acc0[2], acc0[1] + acc0[3]);
                *(float2*)&CRED(credf, kh, crow, n0w + 8 + ccol) =
                    make_float2(acc1[0] + acc1[2], acc1[1] + acc1[3]);
            }
            __syncthreads();

            // combine A: sigmoid, publish z (smem) and r*h (global packed)
            {
                #pragma unroll
                for (int it = 0; it < 2; it++) {
                    int b = cbA + it * 4;
                    float s = CRED(credf, 0, b, cnA) + CRED(credf, 1, b, cnA)
                            + (it == 0 ? xa0 : xa1);
                    float sig = 1.f / (1.f + __expf(-s));
                    if (cnA < 32) {
                        zbuf[sl * 256 + b * 32 + cnA] = sig;
                    } else {
                        int jl = cnA - 32;
                        float rh = sig * h32[sl * 256 + b * 32 + jl];
                        __nv_bfloat16 hi = __float2bfloat16(rh);
                        __nv_bfloat16 lo = __float2bfloat16(rh - __bfloat162float(hi));
                        rhpk_s[sl][b * 512 + j0 + jl] =
                            (unsigned)__bfloat16_as_ushort(hi)
                            | ((unsigned)__bfloat16_as_ushort(lo) << 16);
                    }
                }
            }
            bar_arrive(rhcnt[sl]);            // includes __syncthreads (A-tile reuse safe)
        }

        // =========== phase B for both slabs ===========
        #pragma unroll 1
        for (int sl = 0; sl < 2; sl++) {
            float xb = *pxB[sl];
            pxB[sl] += NG;

            bar_wait(rhcnt[sl], tgt);         // r*h(t) of this slab visible
            // load rh (packed) -> Ahi/Alo
            #pragma unroll
            for (int q = 0; q < 8; q++) {
                uint2 w = *(const uint2*)(rhpk_s[sl] + q * 512 + tid * 2);
                *(uint32_t*)(smem + OFF_AHI + q * WROW + tid * 4) = __byte_perm(w.x, w.y, 0x5410);
                *(uint32_t*)(smem + OFF_ALO + q * WROW + tid * 4) = __byte_perm(w.x, w.y, 0x7632);
            }
            __syncthreads();

            // phase B mma: h~ preacts, N32
            {
                float acc[4] = {0.f, 0.f, 0.f, 0.f};
                #pragma unroll
                for (int k16 = 0; k16 < 16; k16++) {
                    uint32_t off = (uint32_t)(k16 * 32);
                    uint32_t a[4], bh[2], bl[2];
                    LDM_X4(a[0], a[1], a[2], a[3], aA + off);
                    LDM_X2(bh[0], bh[1], bWH + off);
                    LDM_X2(bl[0], bl[1], bWL + off);
                    MMA16816(acc, a, bh);
                    MMA16816(acc, a, bl);
                }
                int n0w = (wid & 3) * 8;
                *(float2*)&CRED(credf, kh, crow, n0w + ccol) =
                    make_float2(acc[0] + acc[2], acc[1] + acc[3]);
            }
            __syncthreads();

            // combine B: tanh, blend, publish h
            {
                float s = CRED(credf, 0, cbB, cjB) + CRED(credf, 1, cbB, cjB) + xb;
                float ht = tanhf(s);
                float hp = h32[sl * 256 + tid];
                float z  = zbuf[sl * 256 + tid];
                float hn = hp + z * (ht - hp);
                h32[sl * 256 + tid] = hn;
                __nv_bfloat16 hi = __float2bfloat16(hn);
                __nv_bfloat16 lo = __float2bfloat16(hn - __bfloat162float(hi));
                hpk_s[sl][cbB * 512 + j0 + cjB] =
                    (unsigned)__bfloat16_as_ushort(hi)
                    | ((unsigned)__bfloat16_as_ushort(lo) << 16);
                size_t hrow = ((size_t)(b0s[sl] + cbB) * SEQ + t) * HDIM + j0 + cjB;
                g_Hh[hrow] = hi;
                g_Hl[hrow] = lo;
                if (t == SEQ - 1)
                    out[(size_t)BATCH * SEQ * BDIM + (b0s[sl] + cbB) * HDIM + j0 + cjB] = hn;
            }
            bar_arrive(hcnt[sl]);             // h(t+1) published
        }

        tgt += 16;
    }
}

// =====================================================================================
extern "C" void kernel_launch(void* const* d_in, const int* in_sizes, int n_in,
                              void* d_out, int out_size)
{
    (void)in_sizes; (void)n_in; (void)out_size;
    const float* x  = (const float*)d_in[0];
    const float* Wz = (const float*)d_in[1];
    const float* bz = (const float*)d_in[2];
    const float* Wr = (const float*)d_in[3];
    const float* br = (const float*)d_in[4];
    const float* Wh = (const float*)d_in[5];
    const float* bh = (const float*)d_in[6];
    const float* Wb = (const float*)d_in[7];
    const float* bb = (const float*)d_in[8];
    float* out = (float*)d_out;

    cudaFuncSetAttribute(recurrent_tc_kernel,
                         cudaFuncAttributeMaxDynamicSharedMemorySize, SMEM2_TOTAL);
    cudaFuncSetAttribute(gemm_mma_kernel,
                         cudaFuncAttributeMaxDynamicSharedMemorySize, GEMM_SMEM);

    __nv_bfloat16 *Xh, *Xl, *Wxh, *Wxl, *Hh, *Hl, *Wbh, *Wbl;
    float *XG, *bcat;
    unsigned* barp;
    cudaGetSymbolAddress((void**)&Xh,  g_Xh);
    cudaGetSymbolAddress((void**)&Xl,  g_Xl);
    cudaGetSymbolAddress((void**)&Wxh, g_Wxh);
    cudaGetSymbolAddress((void**)&Wxl, g_Wxl);
    cudaGetSymbolAddress((void**)&Hh,  g_Hh);
    cudaGetSymbolAddress((void**)&Hl,  g_Hl);
    cudaGetSymbolAddress((void**)&Wbh, g_Wbh);
    cudaGetSymbolAddress((void**)&Wbl, g_Wbl);
    cudaGetSymbolAddress((void**)&XG,  g_XG);
    cudaGetSymbolAddress((void**)&bcat, g_bcat);
    cudaGetSymbolAddress((void**)&barp, g_bar2);

    // Prep: bf16 hi/lo splits
    prep_wx_kernel<<<(NG * XPART + 255) / 256, 256>>>(Wz, Wr, Wh, bz, br, bh);
    prep_wb_kernel<<<(BDIM * HDIM + 255) / 256, 256>>>(Wb);
    prep_x_kernel<<<(M_TOTAL * XPART / 4) / 256, 256>>>(x);

    // Stage 1: XG = xcat @ Wx^T + bcat  (24 super-chunks)
    gemm_mma_kernel<<<dim3(NG / 128, M_TOTAL / 128), 256, GEMM_SMEM>>>(
        Xh, Xl, XPART, Wxh, Wxl, XPART, bcat, XG, NG, XPART / 32);

    // Stage 2: dual-slab persistent recurrence
    cudaMemsetAsync(barp, 0, 8 * 64 * sizeof(unsigned));
    recurrent_tc_kernel<<<NBLK2, 256, SMEM2_TOTAL>>>(Wz, Wr, Wh, out);

    // Stage 3: out = H @ Wb^T + bb  (16 super-chunks)
    gemm_mma_kernel<<<dim3(BDIM / 128, M_TOTAL / 128), 256, GEMM_SMEM>>>(
        Hh, Hl, HDIM, Wbh, Wbl, HDIM, bb, out, BDIM, HDIM / 32);
}

// round 14
// speedup vs baseline: 2.9439x; 2.9439x over previous
#include <cuda_runtime.h>
#include <cuda_bf16.h>
#include <cstdint>
#include <cstddef>

// Problem constants
#define BATCH   64
#define SEQ     2048
#define IDIM    256
#define HDIM    512
#define BDIM    256
#define INDIM   1280     // 3*IDIM + HDIM
#define XPART   768      // 3*IDIM
#define M_TOTAL (BATCH * SEQ)   // 131072
#define NG      1536     // 3 gates * HDIM

#define NBLK2   128      // persistent recurrent grid (1 CTA/SM -> co-resident)

// -------------------- scratch (static __device__, allocation-free) --------------------
__device__ float g_XG[(size_t)M_TOTAL * NG];        // [b*SEQ+t][1536]: xz | xr | xh pre-acts
__device__ unsigned g_cnt8[8 * 32];                 // per-batch-slab barrier counters (padded)

// packed bf16 hi|lo exchange buffers (u32 = hi | lo<<16)
__device__ unsigned g_hpk [BATCH * HDIM];           // h_t
__device__ unsigned g_rhpk[BATCH * HDIM];           // r*h

// bf16 split operands
__device__ __nv_bfloat16 g_Xh[(size_t)M_TOTAL * XPART];   // x concat hi, [b*SEQ+t][768]
__device__ __nv_bfloat16 g_Xl[(size_t)M_TOTAL * XPART];
__device__ __nv_bfloat16 g_Wxh[(size_t)NG * XPART];       // [1536][768] x-part of Wz|Wr|Wh
__device__ __nv_bfloat16 g_Wxl[(size_t)NG * XPART];
__device__ __nv_bfloat16 g_Hh[(size_t)M_TOTAL * HDIM];    // hidden states, [b*SEQ+t][512]
__device__ __nv_bfloat16 g_Hl[(size_t)M_TOTAL * HDIM];
__device__ __nv_bfloat16 g_Wbh[(size_t)BDIM * HDIM];
__device__ __nv_bfloat16 g_Wbl[(size_t)BDIM * HDIM];
__device__ float g_bcat[NG];

// =====================================================================================
// MMA / ldmatrix / cp.async macros (portable sm_80+ PTX)
// =====================================================================================
#define LDM_X4(r0, r1, r2, r3, a) \
    asm volatile("ldmatrix.sync.aligned.m8n8.x4.shared.b16 {%0,%1,%2,%3}, [%4];" \
                 : "=r"(r0), "=r"(r1), "=r"(r2), "=r"(r3) : "r"(a))
#define LDM_X2(r0, r1, a) \
    asm volatile("ldmatrix.sync.aligned.m8n8.x2.shared.b16 {%0,%1}, [%2];" \
                 : "=r"(r0), "=r"(r1) : "r"(a))
#define MMA16816(d, a, b) \
    asm volatile("mma.sync.aligned.m16n8k16.row.col.f32.bf16.bf16.f32 " \
                 "{%0,%1,%2,%3}, {%4,%5,%6,%7}, {%8,%9}, {%0,%1,%2,%3};" \
                 : "+f"((d)[0]), "+f"((d)[1]), "+f"((d)[2]), "+f"((d)[3]) \
                 : "r"((a)[0]), "r"((a)[1]), "r"((a)[2]), "r"((a)[3]), \
                   "r"((b)[0]), "r"((b)[1]))
#define CP_ASYNC16(dst, src) \
    asm volatile("cp.async.cg.shared.global [%0], [%1], 16;" :: "r"(dst), "l"(src))
#define CP_COMMIT() asm volatile("cp.async.commit_group;" ::: "memory")
#define CP_WAIT1()  asm volatile("cp.async.wait_group 1;" ::: "memory")
#define CP_WAIT0()  asm volatile("cp.async.wait_group 0;" ::: "memory")

__device__ __forceinline__ uint32_t smem_u32(const void* p) {
    uint32_t a;
    asm("{ .reg .u64 t; cvta.to.shared.u64 t, %1; cvt.u32.u64 %0, t; }" : "=r"(a) : "l"(p));
    return a;
}

// =====================================================================================
// Prep kernels: build bf16 hi/lo split operands
// =====================================================================================
__global__ void __launch_bounds__(256) prep_wx_kernel(
    const float* __restrict__ Wz, const float* __restrict__ Wr, const float* __restrict__ Wh,
    const float* __restrict__ bz, const float* __restrict__ br, const float* __restrict__ bh)
{
    int idx = blockIdx.x * 256 + threadIdx.x;
    if (idx < NG * XPART) {
        int j = idx / XPART, k = idx - j * XPART;
        int gate = j >> 9, jj = j & 511;
        const float* W = (gate == 0) ? Wz : (gate == 1) ? Wr : Wh;
        float v = W[(size_t)jj * INDIM + k];
        __nv_bfloat16 hi = __float2bfloat16(v);
        __nv_bfloat16 lo = __float2bfloat16(v - __bfloat162float(hi));
        g_Wxh[idx] = hi; g_Wxl[idx] = lo;
    }
    if (idx < NG) {
        g_bcat[idx] = (idx < 512) ? bz[idx] : (idx < 1024) ? br[idx - 512] : bh[idx - 1024];
    }
}

__global__ void __launch_bounds__(256) prep_wb_kernel(const float* __restrict__ Wb)
{
    int idx = blockIdx.x * 256 + threadIdx.x;
    if (idx < BDIM * HDIM) {
        float v = Wb[idx];
        __nv_bfloat16 hi = __float2bfloat16(v);
        __nv_bfloat16 lo = __float2bfloat16(v - __bfloat162float(hi));
        g_Wbh[idx] = hi; g_Wbl[idx] = lo;
    }
}

// x (b, s, t, i) -> Xh/Xl[(b*SEQ+t)*768 + s*256 + i]
__global__ void __launch_bounds__(256) prep_x_kernel(const float* __restrict__ x)
{
    int idx = blockIdx.x * 256 + threadIdx.x;      // one float4
    size_t e = (size_t)idx * 4;
    int b = (int)(e / 1572864);                    // 3*2048*256
    int r = (int)(e - (size_t)b * 1572864);
    int s = r / 524288;                            // 2048*256
    int r2 = r - s * 524288;
    int t = r2 >> 8, i = r2 & 255;
    float4 v = *(const float4*)(x + e);
    size_t dst = ((size_t)b * SEQ + t) * XPART + s * 256 + i;
    __nv_bfloat16 hx = __float2bfloat16(v.x), hy = __float2bfloat16(v.y);
    __nv_bfloat16 hz = __float2bfloat16(v.z), hw = __float2bfloat16(v.w);
    *(__nv_bfloat162*)(g_Xh + dst)     = __nv_bfloat162(hx, hy);
    *(__nv_bfloat162*)(g_Xh + dst + 2) = __nv_bfloat162(hz, hw);
    *(__nv_bfloat162*)(g_Xl + dst)     = __nv_bfloat162(
        __float2bfloat16(v.x - __bfloat162float(hx)), __float2bfloat16(v.y - __bfloat162float(hy)));
    *(__nv_bfloat162*)(g_Xl + dst + 2) = __nv_bfloat162(
        __float2bfloat16(v.z - __bfloat162float(hz)), __float2bfloat16(v.w - __bfloat162float(hw)));
}

// =====================================================================================
// cp.async double-buffered SUPER-CHUNK mma.sync GEMM (stages 1 & 3) — round-10 version.
// =====================================================================================
#define GSTRIDE 80                      // smem row stride bytes (32 bf16 data + 8 pad)
#define G_TILE  (128 * GSTRIDE)         // 10240
#define G_STAGE (4 * G_TILE)            // 40960: Ah | Al | Bh | Bl
#define GEMM_SMEM (2 * G_STAGE)         // 81920

__global__ void __launch_bounds__(256, 2) gemm_mma_kernel(
    const __nv_bfloat16* __restrict__ Ah, const __nv_bfloat16* __restrict__ Al, int lda,
    const __nv_bfloat16* __restrict__ Bh, const __nv_bfloat16* __restrict__ Bl, int ldb,
    const float* __restrict__ bias, float* __restrict__ C, int ldc, int K32)
{
    extern __shared__ char gsm[];
    const uint32_t sbase = smem_u32(gsm);

    const int tid  = threadIdx.x;
    const int wid  = tid >> 5;
    const int lane = tid & 31;
    const int n0   = blockIdx.x * 128;
    const int m0   = blockIdx.y * 128;
    const int m0w  = (wid & 1) * 64;
    const int n0w  = (wid >> 1) * 32;

    const int NC = K32;                 // super-chunks

    const uint32_t a_base = (uint32_t)(((lane & 7) + ((lane >> 3) & 1) * 8) * GSTRIDE
                                       + ((lane >> 4) & 1) * 16);
    const uint32_t b_base = (uint32_t)(((lane & 7) + ((lane >> 4) & 1) * 8) * GSTRIDE
                                       + ((lane >> 3) & 1) * 16);

    float acc[4][4][4];
    #pragma unroll
    for (int i = 0; i < 4; i++)
        #pragma unroll
        for (int j = 0; j < 4; j++)
            #pragma unroll
            for (int q = 0; q < 4; q++) acc[i][j][q] = 0.f;

    auto issue = [&](int c) {
        const int kk = c * 32;
        const uint32_t sb = sbase + (uint32_t)((c & 1) * G_STAGE);
        const int u = tid, row = u >> 2, c16 = u & 3;
        #pragma unroll
        for (int i = 0; i < 2; i++) {
            int rr = row + i * 64;
            uint32_t so = (uint32_t)(rr * GSTRIDE + c16 * 16);
            size_t goA = (size_t)(m0 + rr) * lda + kk + c16 * 8;
            size_t goB = (size_t)(n0 + rr) * ldb + kk + c16 * 8;
            CP_ASYNC16(sb + so,              Ah + goA);
            CP_ASYNC16(sb + G_TILE + so,     Al + goA);
            CP_ASYNC16(sb + 2*G_TILE + so,   Bh + goB);
            CP_ASYNC16(sb + 3*G_TILE + so,   Bl + goB);
        }
        CP_COMMIT();
    };

    issue(0);

    #pragma unroll 1
    for (int c = 0; c < NC; c++) {
        if (c + 1 < NC) { issue(c + 1); CP_WAIT1(); } else { CP_WAIT0(); }
        __syncthreads();

        const uint32_t sb  = sbase + (uint32_t)((c & 1) * G_STAGE);
        const uint32_t sAh = sb + (uint32_t)(m0w * GSTRIDE) + a_base;
        const uint32_t sAl = sAh + G_TILE;
        const uint32_t sBh = sb + 2*G_TILE + (uint32_t)(n0w * GSTRIDE) + b_base;
        const uint32_t sBl = sBh + G_TILE;

        #pragma unroll
        for (int ks = 0; ks < 2; ks++) {
            const uint32_t ko = (uint32_t)(ks * 32);
            uint32_t ahf[4][4], bhf[4][2];
            #pragma unroll
            for (int mb = 0; mb < 4; mb++)
                LDM_X4(ahf[mb][0], ahf[mb][1], ahf[mb][2], ahf[mb][3],
                       sAh + (uint32_t)(mb * 16 * GSTRIDE) + ko);
            #pragma unroll
            for (int q = 0; q < 2; q++)
                LDM_X4(bhf[2*q][0], bhf[2*q][1], bhf[2*q+1][0], bhf[2*q+1][1],
                       sBh + (uint32_t)(q * 16 * GSTRIDE) + ko);
            #pragma unroll
            for (int mb = 0; mb < 4; mb++)
                #pragma unroll
                for (int nb = 0; nb < 4; nb++)
                    MMA16816(acc[mb][nb], ahf[mb], bhf[nb]);     // Ah*Bh

            uint32_t alf[4][4];
            #pragma unroll
            for (int mb = 0; mb < 4; mb++)
                LDM_X4(alf[mb][0], alf[mb][1], alf[mb][2], alf[mb][3],
                       sAl + (uint32_t)(mb * 16 * GSTRIDE) + ko);
            #pragma unroll
            for (int mb = 0; mb < 4; mb++)
                #pragma unroll
                for (int nb = 0; nb < 4; nb++)
                    MMA16816(acc[mb][nb], alf[mb], bhf[nb]);     // Al*Bh

            uint32_t blf[4][2];
            #pragma unroll
            for (int q = 0; q < 2; q++)
                LDM_X4(blf[2*q][0], blf[2*q][1], blf[2*q+1][0], blf[2*q+1][1],
                       sBl + (uint32_t)(q * 16 * GSTRIDE) + ko);
            #pragma unroll
            for (int mb = 0; mb < 4; mb++)
                #pragma unroll
                for (int nb = 0; nb < 4; nb++)
                    MMA16816(acc[mb][nb], ahf[mb], blf[nb]);     // Ah*Bl
        }
        __syncthreads();
    }

    const int g   = lane >> 2;
    const int tig = lane & 3;
    #pragma unroll
    for (int mb = 0; mb < 4; mb++) {
        #pragma unroll
        for (int nb = 0; nb < 4; nb++) {
            int col = n0 + n0w + nb * 8 + tig * 2;
            float b0 = bias[col], b1 = bias[col + 1];
            int r0 = m0 + m0w + mb * 16 + g;
            *(float2*)(C + (size_t)r0 * ldc + col) =
                make_float2(acc[mb][nb][0] + b0, acc[mb][nb][1] + b1);
            *(float2*)(C + (size_t)(r0 + 8) * ldc + col) =
                make_float2(acc[mb][nb][2] + b0, acc[mb][nb][3] + b1);
        }
    }
}

// =====================================================================================
// Stage 2: persistent TENSOR-CORE recurrence — round-10 structure (gbar16 + packed LDG
// exchange) with SPLIT ACCUMULATORS: each MMA accumulator is split 4 ways (k16 parity
// x B-pass) so RAW chains shrink from 32 to 8 MMAs. Pure register-level change.
// =====================================================================================
#define WROW   1040                 // weight/A smem row stride in bytes (520 bf16)
#define OFF_WZRH 0
#define OFF_WZRL (OFF_WZRH + 64*WROW)
#define OFF_WHH  (OFF_WZRL + 64*WROW)
#define OFF_WHL  (OFF_WHH  + 32*WROW)
#define OFF_AHI  (OFF_WHL  + 32*WROW)
#define OFF_ALO  (OFF_AHI  + 8*WROW)
#define OFF_CRED (OFF_ALO  + 8*WROW)
#define OFF_H32  (OFF_CRED + 2*8*66*4)
#define OFF_ZB   (OFF_H32  + 1024)
#define SMEM2_TOTAL (OFF_ZB + 1024)

#define CRED(p, h, r, n) p[((h) * 8 + (r)) * 66 + (n)]

// per-slab barrier: 16 arrivals, monotonic counter (round-8/10 proven primitive)
__device__ __forceinline__ void gbar16(unsigned* cnt, unsigned target) {
    __syncthreads();
    if (threadIdx.x == 0) {
        asm volatile("red.release.gpu.global.add.u32 [%0], %1;" :: "l"(cnt), "r"(1u));
        unsigned c;
        do {
            asm volatile("ld.acquire.gpu.global.u32 %0, [%1];" : "=r"(c) : "l"(cnt));
        } while ((int)(c - target) < 0);
    }
    __syncthreads();
}

__global__ void __launch_bounds__(256, 1) recurrent_tc_kernel(
    const float* __restrict__ Wz, const float* __restrict__ Wr, const float* __restrict__ Wh,
    float* __restrict__ out)
{
    extern __shared__ char smem[];
    const uint32_t sbase = smem_u32(smem);
    float* credf = (float*)(smem + OFF_CRED);
    float* h32   = (float*)(smem + OFF_H32);
    float* zbuf  = (float*)(smem + OFF_ZB);

    const int tid  = threadIdx.x;
    const int wid  = tid >> 5;
    const int lane = tid & 31;
    const int blk  = blockIdx.x;
    const int bslab = blk >> 4;
    const int b0   = bslab * 8;
    const int j0   = (blk & 15) * 32;
    unsigned* mycnt = &g_cnt8[bslab * 32];

    // ---- load + split weights into smem (one-time) ----
    for (int e = tid; e < 64 * 512; e += 256) {
        int row = e >> 9, k = e & 511;
        const float* W = (row < 32) ? Wz : Wr;
        float v = W[(size_t)(j0 + (row & 31)) * INDIM + XPART + k];
        __nv_bfloat16 hi = __float2bfloat16(v);
        __nv_bfloat16 lo = __float2bfloat16(v - __bfloat162float(hi));
        *(__nv_bfloat16*)(smem + OFF_WZRH + row * WROW + k * 2) = hi;
        *(__nv_bfloat16*)(smem + OFF_WZRL + row * WROW + k * 2) = lo;
    }
    for (int e = tid; e < 32 * 512; e += 256) {
        int row = e >> 9, k = e & 511;
        float v = Wh[(size_t)(j0 + row) * INDIM + XPART + k];
        __nv_bfloat16 hi = __float2bfloat16(v);
        __nv_bfloat16 lo = __float2bfloat16(v - __bfloat162float(hi));
        *(__nv_bfloat16*)(smem + OFF_WHH + row * WROW + k * 2) = hi;
        *(__nv_bfloat16*)(smem + OFF_WHL + row * WROW + k * 2) = lo;
    }
    h32[tid] = 0.f;
    g_hpk[(b0 + (tid >> 5)) * HDIM + j0 + (tid & 31)] = 0u;

    unsigned tgt = 16;
    gbar16(mycnt, tgt); tgt += 16;

    // ---- per-warp fragment address bases ----
    const int kh  = wid >> 2;                // K half: 0 -> k[0,256), 1 -> k[256,512)
    const int khB = kh * 512;                // byte offset of K half
    const int arow  = lane & 7;
    const int isLo  = (lane >> 3) & 1;       // lanes 8-15 / 24-31 -> lo rows
    const uint32_t akof = (uint32_t)(((lane >> 4) & 1) * 16);
    const uint32_t aA = sbase + (isLo ? OFF_ALO : OFF_AHI) + arow * WROW + akof + khB;

    const int nsA = wid & 3;                 // phase A N16 slice
    const int browA = nsA * 16 + (lane & 7) + ((lane >> 4) & 1) * 8;
    const uint32_t bkofA = (uint32_t)(((lane >> 3) & 1) * 16);
    const uint32_t bZH = sbase + OFF_WZRH + browA * WROW + bkofA + khB;
    const uint32_t bZL = sbase + OFF_WZRL + browA * WROW + bkofA + khB;

    const int browB = (wid & 3) * 8 + (lane & 7);   // phase B N8 slice
    const uint32_t bkofB = (uint32_t)(((lane >> 3) & 1) * 16);
    const uint32_t bWH = sbase + OFF_WHH + browB * WROW + bkofB + khB;
    const uint32_t bWL = sbase + OFF_WHL + browB * WROW + bkofB + khB;

    // combine mappings + running XG pointers
    const int cbA = tid >> 6;                // combine A: batches cbA and cbA+4
    const int cnA = tid & 63;                // 0..31 -> z, 32..63 -> r
    const int colA = (cnA < 32) ? (j0 + cnA) : (512 + j0 + (cnA - 32));
    const float* pxA0 = g_XG + (size_t)(b0 + cbA)     * SEQ * NG + colA;
    const float* pxA1 = g_XG + (size_t)(b0 + cbA + 4) * SEQ * NG + colA;
    const int cbB = tid >> 5, cjB = tid & 31;
    const float* pxB = g_XG + (size_t)(b0 + cbB) * SEQ * NG + 1024 + j0 + cjB;

    const int crow = lane >> 2;              // C frag row (0..7)
    const int ccol = (lane & 3) * 2;

    unsigned* hpk_my  = g_hpk  + (size_t)b0 * HDIM;
    unsigned* rhpk_my = g_rhpk + (size_t)b0 * HDIM;

    #pragma unroll 1
    for (int t = 0; t < SEQ; t++) {
        // prefetch XG for this step
        float xa0 = *pxA0, xa1 = *pxA1, xb = *pxB;
        pxA0 += NG; pxA1 += NG; pxB += NG;

        // ---- load h (packed) -> Ahi/Alo ----
        #pragma unroll
        for (int q = 0; q < 8; q++) {
            uint2 w = *(const uint2*)(hpk_my + q * 512 + tid * 2);
            *(uint32_t*)(smem + OFF_AHI + q * WROW + tid * 4) = __byte_perm(w.x, w.y, 0x5410);
            *(uint32_t*)(smem + OFF_ALO + q * WROW + tid * 4) = __byte_perm(w.x, w.y, 0x7632);
        }
        __syncthreads();

        // ---- phase A mma: z|r preacts, N64; 4-way split accumulators ----
        {
            float a0h[2][4], a0l[2][4], a1h[2][4], a1l[2][4];
            #pragma unroll
            for (int p = 0; p < 2; p++)
                #pragma unroll
                for (int q = 0; q < 4; q++) {
                    a0h[p][q] = 0.f; a0l[p][q] = 0.f;
                    a1h[p][q] = 0.f; a1l[p][q] = 0.f;
                }
            #pragma unroll
            for (int k16 = 0; k16 < 16; k16++) {
                const int p = k16 & 1;
                uint32_t off = (uint32_t)(k16 * 32);
                uint32_t a[4], bh[4], bl[4];
                LDM_X4(a[0], a[1], a[2], a[3], aA + off);
                LDM_X4(bh[0], bh[1], bh[2], bh[3], bZH + off);
                LDM_X4(bl[0], bl[1], bl[2], bl[3], bZL + off);
                MMA16816(a0h[p], a, bh);
                MMA16816(a1h[p], a, bh + 2);
                MMA16816(a0l[p], a, bl);
                MMA16816(a1l[p], a, bl + 2);
            }
            int n0w = nsA * 16;
            float s00 = a0h[0][0] + a0h[1][0] + a0l[0][0] + a0l[1][0]
                      + a0h[0][2] + a0h[1][2] + a0l[0][2] + a0l[1][2];
            float s01 = a0h[0][1] + a0h[1][1] + a0l[0][1] + a0l[1][1]
                      + a0h[0][3] + a0h[1][3] + a0l[0][3] + a0l[1][3];
            float s10 = a1h[0][0] + a1h[1][0] + a1l[0][0] + a1l[1][0]
                      + a1h[0][2] + a1h[1][2] + a1l[0][2] + a1l[1][2];
            float s11 = a1h[0][1] + a1h[1][1] + a1l[0][1] + a1l[1][1]
                      + a1h[0][3] + a1h[1][3] + a1l[0][3] + a1l[1][3];
            *(float2*)&CRED(credf, kh, crow, n0w + ccol)     = make_float2(s00, s01);
            *(float2*)&CRED(credf, kh, crow, n0w + 8 + ccol) = make_float2(s10, s11);
        }
        __syncthreads();

        // ---- combine A: sigmoid, publish z (smem) and r*h (global packed) ----
        {
            #pragma unroll
            for (int it = 0; it < 2; it++) {
                int b = cbA + it * 4;
                float s = CRED(credf, 0, b, cnA) + CRED(credf, 1, b, cnA)
                        + (it == 0 ? xa0 : xa1);
                float sig = 1.f / (1.f + __expf(-s));
                if (cnA < 32) {
                    zbuf[b * 32 + cnA] = sig;
                } else {
                    int jl = cnA - 32;
                    float rh = sig * h32[b * 32 + jl];
                    __nv_bfloat16 hi = __float2bfloat16(rh);
                    __nv_bfloat16 lo = __float2bfloat16(rh - __bfloat162float(hi));
                    rhpk_my[b * 512 + j0 + jl] =
                        (unsigned)__bfloat16_as_ushort(hi)
                        | ((unsigned)__bfloat16_as_ushort(lo) << 16);
                }
            }
        }
        gbar16(mycnt, tgt); tgt += 16;

        // ---- load rh (packed) -> Ahi/Alo ----
        #pragma unroll
        for (int q = 0; q < 8; q++) {
            uint2 w = *(const uint2*)(rhpk_my + q * 512 + tid * 2);
            *(uint32_t*)(smem + OFF_AHI + q * WROW + tid * 4) = __byte_perm(w.x, w.y, 0x5410);
            *(uint32_t*)(smem + OFF_ALO + q * WROW + tid * 4) = __byte_perm(w.x, w.y, 0x7632);
        }
        __syncthreads();

        // ---- phase B mma: h~ preacts, N32; 4-way split accumulators ----
        {
            float ah[2][4], al[2][4];
            #pragma unroll
            for (int p = 0; p < 2; p++)
                #pragma unroll
                for (int q = 0; q < 4; q++) { ah[p][q] = 0.f; al[p][q] = 0.f; }
            #pragma unroll
            for (int k16 = 0; k16 < 16; k16++) {
                const int p = k16 & 1;
                uint32_t off = (uint32_t)(k16 * 32);
                uint32_t a[4], bh[2], bl[2];
                LDM_X4(a[0], a[1], a[2], a[3], aA + off);
                LDM_X2(bh[0], bh[1], bWH + off);
                LDM_X2(bl[0], bl[1], bWL + off);
                MMA16816(ah[p], a, bh);
                MMA16816(al[p], a, bl);
            }
            int n0w = (wid & 3) * 8;
            float s0 = ah[0][0] + ah[1][0] + al[0][0] + al[1][0]
                     + ah[0][2] + ah[1][2] + al[0][2] + al[1][2];
            float s1 = ah[0][1] + ah[1][1] + al[0][1] + al[1][1]
                     + ah[0][3] + ah[1][3] + al[0][3] + al[1][3];
            *(float2*)&CRED(credf, kh, crow, n0w + ccol) = make_float2(s0, s1);
        }
        __syncthreads();

        // ---- combine B: tanh, blend, publish h ----
        {
            float s = CRED(credf, 0, cbB, cjB) + CRED(credf, 1, cbB, cjB) + xb;
            float ht = tanhf(s);
            float hp = h32[tid];
            float z  = zbuf[tid];
            float hn = hp + z * (ht - hp);
            h32[tid] = hn;
            __nv_bfloat16 hi = __float2bfloat16(hn);
            __nv_bfloat16 lo = __float2bfloat16(hn - __bfloat162float(hi));
            hpk_my[cbB * 512 + j0 + cjB] =
                (unsigned)__bfloat16_as_ushort(hi) | ((unsigned)__bfloat16_as_ushort(lo) << 16);
            size_t hrow = ((size_t)(b0 + cbB) * SEQ + t) * HDIM + j0 + cjB;
            g_Hh[hrow] = hi;
            g_Hl[hrow] = lo;
            if (t == SEQ - 1)
                out[(size_t)BATCH * SEQ * BDIM + (b0 + cbB) * HDIM + j0 + cjB] = hn;
        }
        gbar16(mycnt, tgt); tgt += 16;
    }
}

// =====================================================================================
extern "C" void kernel_launch(void* const* d_in, const int* in_sizes, int n_in,
                              void* d_out, int out_size)
{
    (void)in_sizes; (void)n_in; (void)out_size;
    const float* x  = (const float*)d_in[0];
    const float* Wz = (const float*)d_in[1];
    const float* bz = (const float*)d_in[2];
    const float* Wr = (const float*)d_in[3];
    const float* br = (const float*)d_in[4];
    const float* Wh = (const float*)d_in[5];
    const float* bh = (const float*)d_in[6];
    const float* Wb = (const float*)d_in[7];
    const float* bb = (const float*)d_in[8];
    float* out = (float*)d_out;

    cudaFuncSetAttribute(recurrent_tc_kernel,
                         cudaFuncAttributeMaxDynamicSharedMemorySize, SMEM2_TOTAL);
    cudaFuncSetAttribute(gemm_mma_kernel,
                         cudaFuncAttributeMaxDynamicSharedMemorySize, GEMM_SMEM);

    __nv_bfloat16 *Xh, *Xl, *Wxh, *Wxl, *Hh, *Hl, *Wbh, *Wbl;
    float *XG, *bcat;
    unsigned* cntp;
    cudaGetSymbolAddress((void**)&Xh,  g_Xh);
    cudaGetSymbolAddress((void**)&Xl,  g_Xl);
    cudaGetSymbolAddress((void**)&Wxh, g_Wxh);
    cudaGetSymbolAddress((void**)&Wxl, g_Wxl);
    cudaGetSymbolAddress((void**)&Hh,  g_Hh);
    cudaGetSymbolAddress((void**)&Hl,  g_Hl);
    cudaGetSymbolAddress((void**)&Wbh, g_Wbh);
    cudaGetSymbolAddress((void**)&Wbl, g_Wbl);
    cudaGetSymbolAddress((void**)&XG,  g_XG);
    cudaGetSymbolAddress((void**)&bcat, g_bcat);
    cudaGetSymbolAddress((void**)&cntp, g_cnt8);

    // Prep: bf16 hi/lo splits
    prep_wx_kernel<<<(NG * XPART + 255) / 256, 256>>>(Wz, Wr, Wh, bz, br, bh);
    prep_wb_kernel<<<(BDIM * HDIM + 255) / 256, 256>>>(Wb);
    prep_x_kernel<<<(M_TOTAL * XPART / 4) / 256, 256>>>(x);

    // Stage 1: XG = xcat @ Wx^T + bcat  (24 super-chunks)
    gemm_mma_kernel<<<dim3(NG / 128, M_TOTAL / 128), 256, GEMM_SMEM>>>(
        Xh, Xl, XPART, Wxh, Wxl, XPART, bcat, XG, NG, XPART / 32);

    // Stage 2: persistent tensor-core recurrence (writes g_Hh/g_Hl + h_fin tail)
    cudaMemsetAsync(cntp, 0, 8 * 32 * sizeof(unsigned));
    recurrent_tc_kernel<<<NBLK2, 256, SMEM2_TOTAL>>>(Wz, Wr, Wh, out);

    // Stage 3: out = H @ Wb^T + bb  (16 super-chunks)
    gemm_mma_kernel<<<dim3(BDIM / 128, M_TOTAL / 128), 256, GEMM_SMEM>>>(
        Hh, Hl, HDIM, Wbh, Wbl, HDIM, bb, out, BDIM, HDIM / 32);
}

// round 15
// speedup vs baseline: 2.9797x; 1.0121x over previous
#include <cuda_runtime.h>
#include <cuda_bf16.h>
#include <cstdint>
#include <cstddef>

// Problem constants
#define BATCH   64
#define SEQ     2048
#define IDIM    256
#define HDIM    512
#define BDIM    256
#define INDIM   1280     // 3*IDIM + HDIM
#define XPART   768      // 3*IDIM
#define M_TOTAL (BATCH * SEQ)   // 131072
#define NG      1536     // 3 gates * HDIM

#define NBLK2   128      // persistent recurrent grid (1 CTA/SM -> co-resident)

// -------------------- scratch (static __device__, allocation-free) --------------------
__device__ float g_XG[(size_t)M_TOTAL * NG];        // [b*SEQ+t][1536]: xz | xr | xh pre-acts
__device__ unsigned g_cnt8[8 * 32];                 // per-batch-slab barrier counters (padded)

// packed bf16 hi|lo exchange buffers (u32 = hi | lo<<16)
__device__ unsigned g_hpk [BATCH * HDIM];           // h_t
__device__ unsigned g_rhpk[BATCH * HDIM];           // r*h

// bf16 split operands
__device__ __nv_bfloat16 g_Xh[(size_t)M_TOTAL * XPART];   // x concat hi, [b*SEQ+t][768]
__device__ __nv_bfloat16 g_Xl[(size_t)M_TOTAL * XPART];
__device__ __nv_bfloat16 g_Wxh[(size_t)NG * XPART];       // [1536][768] x-part of Wz|Wr|Wh
__device__ __nv_bfloat16 g_Wxl[(size_t)NG * XPART];
__device__ __nv_bfloat16 g_Hh[(size_t)M_TOTAL * HDIM];    // hidden states, [b*SEQ+t][512]
__device__ __nv_bfloat16 g_Hl[(size_t)M_TOTAL * HDIM];
__device__ __nv_bfloat16 g_Wbh[(size_t)BDIM * HDIM];
__device__ __nv_bfloat16 g_Wbl[(size_t)BDIM * HDIM];
__device__ float g_bcat[NG];

// =====================================================================================
// MMA / ldmatrix / cp.async macros (portable sm_80+ PTX)
// =====================================================================================
#define LDM_X4(r0, r1, r2, r3, a) \
    asm volatile("ldmatrix.sync.aligned.m8n8.x4.shared.b16 {%0,%1,%2,%3}, [%4];" \
                 : "=r"(r0), "=r"(r1), "=r"(r2), "=r"(r3) : "r"(a))
#define LDM_X2(r0, r1, a) \
    asm volatile("ldmatrix.sync.aligned.m8n8.x2.shared.b16 {%0,%1}, [%2];" \
                 : "=r"(r0), "=r"(r1) : "r"(a))
#define MMA16816(d, a, b) \
    asm volatile("mma.sync.aligned.m16n8k16.row.col.f32.bf16.bf16.f32 " \
                 "{%0,%1,%2,%3}, {%4,%5,%6,%7}, {%8,%9}, {%0,%1,%2,%3};" \
                 : "+f"((d)[0]), "+f"((d)[1]), "+f"((d)[2]), "+f"((d)[3]) \
                 : "r"((a)[0]), "r"((a)[1]), "r"((a)[2]), "r"((a)[3]), \
                   "r"((b)[0]), "r"((b)[1]))
#define CP_ASYNC16(dst, src) \
    asm volatile("cp.async.cg.shared.global [%0], [%1], 16;" :: "r"(dst), "l"(src))
#define CP_COMMIT() asm volatile("cp.async.commit_group;" ::: "memory")
#define CP_WAIT1()  asm volatile("cp.async.wait_group 1;" ::: "memory")
#define CP_WAIT0()  asm volatile("cp.async.wait_group 0;" ::: "memory")

__device__ __forceinline__ uint32_t smem_u32(const void* p) {
    uint32_t a;
    asm("{ .reg .u64 t; cvta.to.shared.u64 t, %1; cvt.u32.u64 %0, t; }" : "=r"(a) : "l"(p));
    return a;
}

// =====================================================================================
// Prep kernels: build bf16 hi/lo split operands
// =====================================================================================
__global__ void __launch_bounds__(256) prep_wx_kernel(
    const float* __restrict__ Wz, const float* __restrict__ Wr, const float* __restrict__ Wh,
    const float* __restrict__ bz, const float* __restrict__ br, const float* __restrict__ bh)
{
    int idx = blockIdx.x * 256 + threadIdx.x;
    if (idx < NG * XPART) {
        int j = idx / XPART, k = idx - j * XPART;
        int gate = j >> 9, jj = j & 511;
        const float* W = (gate == 0) ? Wz : (gate == 1) ? Wr : Wh;
        float v = W[(size_t)jj * INDIM + k];
        __nv_bfloat16 hi = __float2bfloat16(v);
        __nv_bfloat16 lo = __float2bfloat16(v - __bfloat162float(hi));
        g_Wxh[idx] = hi; g_Wxl[idx] = lo;
    }
    if (idx < NG) {
        g_bcat[idx] = (idx < 512) ? bz[idx] : (idx < 1024) ? br[idx - 512] : bh[idx - 1024];
    }
}

__global__ void __launch_bounds__(256) prep_wb_kernel(const float* __restrict__ Wb)
{
    int idx = blockIdx.x * 256 + threadIdx.x;
    if (idx < BDIM * HDIM) {
        float v = Wb[idx];
        __nv_bfloat16 hi = __float2bfloat16(v);
        __nv_bfloat16 lo = __float2bfloat16(v - __bfloat162float(hi));
        g_Wbh[idx] = hi; g_Wbl[idx] = lo;
    }
}

// x (b, s, t, i) -> Xh/Xl[(b*SEQ+t)*768 + s*256 + i]
__global__ void __launch_bounds__(256) prep_x_kernel(const float* __restrict__ x)
{
    int idx = blockIdx.x * 256 + threadIdx.x;      // one float4
    size_t e = (size_t)idx * 4;
    int b = (int)(e / 1572864);                    // 3*2048*256
    int r = (int)(e - (size_t)b * 1572864);
    int s = r / 524288;                            // 2048*256
    int r2 = r - s * 524288;
    int t = r2 >> 8, i = r2 & 255;
    float4 v = *(const float4*)(x + e);
    size_t dst = ((size_t)b * SEQ + t) * XPART + s * 256 + i;
    __nv_bfloat16 hx = __float2bfloat16(v.x), hy = __float2bfloat16(v.y);
    __nv_bfloat16 hz = __float2bfloat16(v.z), hw = __float2bfloat16(v.w);
    *(__nv_bfloat162*)(g_Xh + dst)     = __nv_bfloat162(hx, hy);
    *(__nv_bfloat162*)(g_Xh + dst + 2) = __nv_bfloat162(hz, hw);
    *(__nv_bfloat162*)(g_Xl + dst)     = __nv_bfloat162(
        __float2bfloat16(v.x - __bfloat162float(hx)), __float2bfloat16(v.y - __bfloat162float(hy)));
    *(__nv_bfloat162*)(g_Xl + dst + 2) = __nv_bfloat162(
        __float2bfloat16(v.z - __bfloat162float(hz)), __float2bfloat16(v.w - __bfloat162float(hw)));
}

// =====================================================================================
// cp.async double-buffered SUPER-CHUNK mma.sync GEMM (stages 1 & 3) — round-10 version.
// =====================================================================================
#define GSTRIDE 80                      // smem row stride bytes (32 bf16 data + 8 pad)
#define G_TILE  (128 * GSTRIDE)         // 10240
#define G_STAGE (4 * G_TILE)            // 40960: Ah | Al | Bh | Bl
#define GEMM_SMEM (2 * G_STAGE)         // 81920

__global__ void __launch_bounds__(256, 2) gemm_mma_kernel(
    const __nv_bfloat16* __restrict__ Ah, const __nv_bfloat16* __restrict__ Al, int lda,
    const __nv_bfloat16* __restrict__ Bh, const __nv_bfloat16* __restrict__ Bl, int ldb,
    const float* __restrict__ bias, float* __restrict__ C, int ldc, int K32)
{
    extern __shared__ char gsm[];
    const uint32_t sbase = smem_u32(gsm);

    const int tid  = threadIdx.x;
    const int wid  = tid >> 5;
    const int lane = tid & 31;
    const int n0   = blockIdx.x * 128;
    const int m0   = blockIdx.y * 128;
    const int m0w  = (wid & 1) * 64;
    const int n0w  = (wid >> 1) * 32;

    const int NC = K32;                 // super-chunks

    const uint32_t a_base = (uint32_t)(((lane & 7) + ((lane >> 3) & 1) * 8) * GSTRIDE
                                       + ((lane >> 4) & 1) * 16);
    const uint32_t b_base = (uint32_t)(((lane & 7) + ((lane >> 4) & 1) * 8) * GSTRIDE
                                       + ((lane >> 3) & 1) * 16);

    float acc[4][4][4];
    #pragma unroll
    for (int i = 0; i < 4; i++)
        #pragma unroll
        for (int j = 0; j < 4; j++)
            #pragma unroll
            for (int q = 0; q < 4; q++) acc[i][j][q] = 0.f;

    auto issue = [&](int c) {
        const int kk = c * 32;
        const uint32_t sb = sbase + (uint32_t)((c & 1) * G_STAGE);
        const int u = tid, row = u >> 2, c16 = u & 3;
        #pragma unroll
        for (int i = 0; i < 2; i++) {
            int rr = row + i * 64;
            uint32_t so = (uint32_t)(rr * GSTRIDE + c16 * 16);
            size_t goA = (size_t)(m0 + rr) * lda + kk + c16 * 8;
            size_t goB = (size_t)(n0 + rr) * ldb + kk + c16 * 8;
            CP_ASYNC16(sb + so,              Ah + goA);
            CP_ASYNC16(sb + G_TILE + so,     Al + goA);
            CP_ASYNC16(sb + 2*G_TILE + so,   Bh + goB);
            CP_ASYNC16(sb + 3*G_TILE + so,   Bl + goB);
        }
        CP_COMMIT();
    };

    issue(0);

    #pragma unroll 1
    for (int c = 0; c < NC; c++) {
        if (c + 1 < NC) { issue(c + 1); CP_WAIT1(); } else { CP_WAIT0(); }
        __syncthreads();

        const uint32_t sb  = sbase + (uint32_t)((c & 1) * G_STAGE);
        const uint32_t sAh = sb + (uint32_t)(m0w * GSTRIDE) + a_base;
        const uint32_t sAl = sAh + G_TILE;
        const uint32_t sBh = sb + 2*G_TILE + (uint32_t)(n0w * GSTRIDE) + b_base;
        const uint32_t sBl = sBh + G_TILE;

        #pragma unroll
        for (int ks = 0; ks < 2; ks++) {
            const uint32_t ko = (uint32_t)(ks * 32);
            uint32_t ahf[4][4], bhf[4][2];
            #pragma unroll
            for (int mb = 0; mb < 4; mb++)
                LDM_X4(ahf[mb][0], ahf[mb][1], ahf[mb][2], ahf[mb][3],
                       sAh + (uint32_t)(mb * 16 * GSTRIDE) + ko);
            #pragma unroll
            for (int q = 0; q < 2; q++)
                LDM_X4(bhf[2*q][0], bhf[2*q][1], bhf[2*q+1][0], bhf[2*q+1][1],
                       sBh + (uint32_t)(q * 16 * GSTRIDE) + ko);
            #pragma unroll
            for (int mb = 0; mb < 4; mb++)
                #pragma unroll
                for (int nb = 0; nb < 4; nb++)
                    MMA16816(acc[mb][nb], ahf[mb], bhf[nb]);     // Ah*Bh

            uint32_t alf[4][4];
            #pragma unroll
            for (int mb = 0; mb < 4; mb++)
                LDM_X4(alf[mb][0], alf[mb][1], alf[mb][2], alf[mb][3],
                       sAl + (uint32_t)(mb * 16 * GSTRIDE) + ko);
            #pragma unroll
            for (int mb = 0; mb < 4; mb++)
                #pragma unroll
                for (int nb = 0; nb < 4; nb++)
                    MMA16816(acc[mb][nb], alf[mb], bhf[nb]);     // Al*Bh

            uint32_t blf[4][2];
            #pragma unroll
            for (int q = 0; q < 2; q++)
                LDM_X4(blf[2*q][0], blf[2*q][1], blf[2*q+1][0], blf[2*q+1][1],
                       sBl + (uint32_t)(q * 16 * GSTRIDE) + ko);
            #pragma unroll
            for (int mb = 0; mb < 4; mb++)
                #pragma unroll
                for (int nb = 0; nb < 4; nb++)
                    MMA16816(acc[mb][nb], ahf[mb], blf[nb]);     // Ah*Bl
        }
        __syncthreads();
    }

    const int g   = lane >> 2;
    const int tig = lane & 3;
    #pragma unroll
    for (int mb = 0; mb < 4; mb++) {
        #pragma unroll
        for (int nb = 0; nb < 4; nb++) {
            int col = n0 + n0w + nb * 8 + tig * 2;
            float b0 = bias[col], b1 = bias[col + 1];
            int r0 = m0 + m0w + mb * 16 + g;
            *(float2*)(C + (size_t)r0 * ldc + col) =
                make_float2(acc[mb][nb][0] + b0, acc[mb][nb][1] + b1);
            *(float2*)(C + (size_t)(r0 + 8) * ldc + col) =
                make_float2(acc[mb][nb][2] + b0, acc[mb][nb][3] + b1);
        }
    }
}

// =====================================================================================
// Stage 2: persistent TENSOR-CORE recurrence — round-14 structure with:
//   (1) tanh.approx.f32 in combine B (1 MUFU instr vs ~25-instr softfloat tanhf)
//   (2) barrier after combine B split into arrive / deferred stores / wait:
//       g_Hh/g_Hl/out stores (not peer-visible) overlap the barrier poll.
// =====================================================================================
#define WROW   1040                 // weight/A smem row stride in bytes (520 bf16)
#define OFF_WZRH 0
#define OFF_WZRL (OFF_WZRH + 64*WROW)
#define OFF_WHH  (OFF_WZRL + 64*WROW)
#define OFF_WHL  (OFF_WHH  + 32*WROW)
#define OFF_AHI  (OFF_WHL  + 32*WROW)
#define OFF_ALO  (OFF_AHI  + 8*WROW)
#define OFF_CRED (OFF_ALO  + 8*WROW)
#define OFF_H32  (OFF_CRED + 2*8*66*4)
#define OFF_ZB   (OFF_H32  + 1024)
#define SMEM2_TOTAL (OFF_ZB + 1024)

#define CRED(p, h, r, n) p[((h) * 8 + (r)) * 66 + (n)]

// per-slab barrier: 16 arrivals, monotonic counter (round-8/10 proven primitive)
__device__ __forceinline__ void gbar16(unsigned* cnt, unsigned target) {
    __syncthreads();
    if (threadIdx.x == 0) {
        asm volatile("red.release.gpu.global.add.u32 [%0], %1;" :: "l"(cnt), "r"(1u));
        unsigned c;
        do {
            asm volatile("ld.acquire.gpu.global.u32 %0, [%1];" : "=r"(c) : "l"(cnt));
        } while ((int)(c - target) < 0);
    }
    __syncthreads();
}
// split halves (same semantics, deferred work can run between them on non-0 threads)
__device__ __forceinline__ void gbar16_arrive(unsigned* cnt) {
    __syncthreads();
    if (threadIdx.x == 0)
        asm volatile("red.release.gpu.global.add.u32 [%0], %1;" :: "l"(cnt), "r"(1u));
}
__device__ __forceinline__ void gbar16_wait(unsigned* cnt, unsigned target) {
    if (threadIdx.x == 0) {
        unsigned c;
        do {
            asm volatile("ld.acquire.gpu.global.u32 %0, [%1];" : "=r"(c) : "l"(cnt));
        } while ((int)(c - target) < 0);
    }
    __syncthreads();
}

__global__ void __launch_bounds__(256, 1) recurrent_tc_kernel(
    const float* __restrict__ Wz, const float* __restrict__ Wr, const float* __restrict__ Wh,
    float* __restrict__ out)
{
    extern __shared__ char smem[];
    const uint32_t sbase = smem_u32(smem);
    float* credf = (float*)(smem + OFF_CRED);
    float* h32   = (float*)(smem + OFF_H32);
    float* zbuf  = (float*)(smem + OFF_ZB);

    const int tid  = threadIdx.x;
    const int wid  = tid >> 5;
    const int lane = tid & 31;
    const int blk  = blockIdx.x;
    const int bslab = blk >> 4;
    const int b0   = bslab * 8;
    const int j0   = (blk & 15) * 32;
    unsigned* mycnt = &g_cnt8[bslab * 32];

    // ---- load + split weights into smem (one-time) ----
    for (int e = tid; e < 64 * 512; e += 256) {
        int row = e >> 9, k = e & 511;
        const float* W = (row < 32) ? Wz : Wr;
        float v = W[(size_t)(j0 + (row & 31)) * INDIM + XPART + k];
        __nv_bfloat16 hi = __float2bfloat16(v);
        __nv_bfloat16 lo = __float2bfloat16(v - __bfloat162float(hi));
        *(__nv_bfloat16*)(smem + OFF_WZRH + row * WROW + k * 2) = hi;
        *(__nv_bfloat16*)(smem + OFF_WZRL + row * WROW + k * 2) = lo;
    }
    for (int e = tid; e < 32 * 512; e += 256) {
        int row = e >> 9, k = e & 511;
        float v = Wh[(size_t)(j0 + row) * INDIM + XPART + k];
        __nv_bfloat16 hi = __float2bfloat16(v);
        __nv_bfloat16 lo = __float2bfloat16(v - __bfloat162float(hi));
        *(__nv_bfloat16*)(smem + OFF_WHH + row * WROW + k * 2) = hi;
        *(__nv_bfloat16*)(smem + OFF_WHL + row * WROW + k * 2) = lo;
    }
    h32[tid] = 0.f;
    g_hpk[(b0 + (tid >> 5)) * HDIM + j0 + (tid & 31)] = 0u;

    unsigned tgt = 16;
    gbar16(mycnt, tgt); tgt += 16;

    // ---- per-warp fragment address bases ----
    const int kh  = wid >> 2;                // K half: 0 -> k[0,256), 1 -> k[256,512)
    const int khB = kh * 512;                // byte offset of K half
    const int arow  = lane & 7;
    const int isLo  = (lane >> 3) & 1;       // lanes 8-15 / 24-31 -> lo rows
    const uint32_t akof = (uint32_t)(((lane >> 4) & 1) * 16);
    const uint32_t aA = sbase + (isLo ? OFF_ALO : OFF_AHI) + arow * WROW + akof + khB;

    const int nsA = wid & 3;                 // phase A N16 slice
    const int browA = nsA * 16 + (lane & 7) + ((lane >> 4) & 1) * 8;
    const uint32_t bkofA = (uint32_t)(((lane >> 3) & 1) * 16);
    const uint32_t bZH = sbase + OFF_WZRH + browA * WROW + bkofA + khB;
    const uint32_t bZL = sbase + OFF_WZRL + browA * WROW + bkofA + khB;

    const int browB = (wid & 3) * 8 + (lane & 7);   // phase B N8 slice
    const uint32_t bkofB = (uint32_t)(((lane >> 3) & 1) * 16);
    const uint32_t bWH = sbase + OFF_WHH + browB * WROW + bkofB + khB;
    const uint32_t bWL = sbase + OFF_WHL + browB * WROW + bkofB + khB;

    // combine mappings + running XG pointers
    const int cbA = tid >> 6;                // combine A: batches cbA and cbA+4
    const int cnA = tid & 63;                // 0..31 -> z, 32..63 -> r
    const int colA = (cnA < 32) ? (j0 + cnA) : (512 + j0 + (cnA - 32));
    const float* pxA0 = g_XG + (size_t)(b0 + cbA)     * SEQ * NG + colA;
    const float* pxA1 = g_XG + (size_t)(b0 + cbA + 4) * SEQ * NG + colA;
    const int cbB = tid >> 5, cjB = tid & 31;
    const float* pxB = g_XG + (size_t)(b0 + cbB) * SEQ * NG + 1024 + j0 + cjB;

    const int crow = lane >> 2;              // C frag row (0..7)
    const int ccol = (lane & 3) * 2;

    unsigned* hpk_my  = g_hpk  + (size_t)b0 * HDIM;
    unsigned* rhpk_my = g_rhpk + (size_t)b0 * HDIM;

    #pragma unroll 1
    for (int t = 0; t < SEQ; t++) {
        // prefetch XG for this step
        float xa0 = *pxA0, xa1 = *pxA1, xb = *pxB;
        pxA0 += NG; pxA1 += NG; pxB += NG;

        // ---- load h (packed) -> Ahi/Alo ----
        #pragma unroll
        for (int q = 0; q < 8; q++) {
            uint2 w = *(const uint2*)(hpk_my + q * 512 + tid * 2);
            *(uint32_t*)(smem + OFF_AHI + q * WROW + tid * 4) = __byte_perm(w.x, w.y, 0x5410);
            *(uint32_t*)(smem + OFF_ALO + q * WROW + tid * 4) = __byte_perm(w.x, w.y, 0x7632);
        }
        __syncthreads();

        // ---- phase A mma: z|r preacts, N64; 4-way split accumulators ----
        {
            float a0h[2][4], a0l[2][4], a1h[2][4], a1l[2][4];
            #pragma unroll
            for (int p = 0; p < 2; p++)
                #pragma unroll
                for (int q = 0; q < 4; q++) {
                    a0h[p][q] = 0.f; a0l[p][q] = 0.f;
                    a1h[p][q] = 0.f; a1l[p][q] = 0.f;
                }
            #pragma unroll
            for (int k16 = 0; k16 < 16; k16++) {
                const int p = k16 & 1;
                uint32_t off = (uint32_t)(k16 * 32);
                uint32_t a[4], bh[4], bl[4];
                LDM_X4(a[0], a[1], a[2], a[3], aA + off);
                LDM_X4(bh[0], bh[1], bh[2], bh[3], bZH + off);
                LDM_X4(bl[0], bl[1], bl[2], bl[3], bZL + off);
                MMA16816(a0h[p], a, bh);
                MMA16816(a1h[p], a, bh + 2);
                MMA16816(a0l[p], a, bl);
                MMA16816(a1l[p], a, bl + 2);
            }
            int n0w = nsA * 16;
            float s00 = a0h[0][0] + a0h[1][0] + a0l[0][0] + a0l[1][0]
                      + a0h[0][2] + a0h[1][2] + a0l[0][2] + a0l[1][2];
            float s01 = a0h[0][1] + a0h[1][1] + a0l[0][1] + a0l[1][1]
                      + a0h[0][3] + a0h[1][3] + a0l[0][3] + a0l[1][3];
            float s10 = a1h[0][0] + a1h[1][0] + a1l[0][0] + a1l[1][0]
                      + a1h[0][2] + a1h[1][2] + a1l[0][2] + a1l[1][2];
            float s11 = a1h[0][1] + a1h[1][1] + a1l[0][1] + a1l[1][1]
                      + a1h[0][3] + a1h[1][3] + a1l[0][3] + a1l[1][3];
            *(float2*)&CRED(credf, kh, crow, n0w + ccol)     = make_float2(s00, s01);
            *(float2*)&CRED(credf, kh, crow, n0w + 8 + ccol) = make_float2(s10, s11);
        }
        __syncthreads();

        // ---- combine A: sigmoid, publish z (smem) and r*h (global packed) ----
        {
            #pragma unroll
            for (int it = 0; it < 2; it++) {
                int b = cbA + it * 4;
                float s = CRED(credf, 0, b, cnA) + CRED(credf, 1, b, cnA)
                        + (it == 0 ? xa0 : xa1);
                float sig = 1.f / (1.f + __expf(-s));
                if (cnA < 32) {
                    zbuf[b * 32 + cnA] = sig;
                } else {
                    int jl = cnA - 32;
                    float rh = sig * h32[b * 32 + jl];
                    __nv_bfloat16 hi = __float2bfloat16(rh);
                    __nv_bfloat16 lo = __float2bfloat16(rh - __bfloat162float(hi));
                    rhpk_my[b * 512 + j0 + jl] =
                        (unsigned)__bfloat16_as_ushort(hi)
                        | ((unsigned)__bfloat16_as_ushort(lo) << 16);
                }
            }
        }
        gbar16(mycnt, tgt); tgt += 16;

        // ---- load rh (packed) -> Ahi/Alo ----
        #pragma unroll
        for (int q = 0; q < 8; q++) {
            uint2 w = *(const uint2*)(rhpk_my + q * 512 + tid * 2);
            *(uint32_t*)(smem + OFF_AHI + q * WROW + tid * 4) = __byte_perm(w.x, w.y, 0x5410);
            *(uint32_t*)(smem + OFF_ALO + q * WROW + tid * 4) = __byte_perm(w.x, w.y, 0x7632);
        }
        __syncthreads();

        // ---- phase B mma: h~ preacts, N32; 4-way split accumulators ----
        {
            float ah[2][4], al[2][4];
            #pragma unroll
            for (int p = 0; p < 2; p++)
                #pragma unroll
                for (int q = 0; q < 4; q++) { ah[p][q] = 0.f; al[p][q] = 0.f; }
            #pragma unroll
            for (int k16 = 0; k16 < 16; k16++) {
                const int p = k16 & 1;
                uint32_t off = (uint32_t)(k16 * 32);
                uint32_t a[4], bh[2], bl[2];
                LDM_X4(a[0], a[1], a[2], a[3], aA + off);
                LDM_X2(bh[0], bh[1], bWH + off);
                LDM_X2(bl[0], bl[1], bWL + off);
                MMA16816(ah[p], a, bh);
                MMA16816(al[p], a, bl);
            }
            int n0w = (wid & 3) * 8;
            float s0 = ah[0][0] + ah[1][0] + al[0][0] + al[1][0]
                     + ah[0][2] + ah[1][2] + al[0][2] + al[1][2];
            float s1 = ah[0][1] + ah[1][1] + al[0][1] + al[1][1]
                     + ah[0][3] + ah[1][3] + al[0][3] + al[1][3];
            *(float2*)&CRED(credf, kh, crow, n0w + ccol) = make_float2(s0, s1);
        }
        __syncthreads();

        // ---- combine B: tanh.approx, blend, publish h (peer-visible first) ----
        float hn;
        __nv_bfloat16 hn_hi, hn_lo;
        {
            float s = CRED(credf, 0, cbB, cjB) + CRED(credf, 1, cbB, cjB) + xb;
            float ht;
            asm("tanh.approx.f32 %0, %1;" : "=f"(ht) : "f"(s));
            float hp = h32[tid];
            float z  = zbuf[tid];
            hn = hp + z * (ht - hp);
            h32[tid] = hn;
            hn_hi = __float2bfloat16(hn);
            hn_lo = __float2bfloat16(hn - __bfloat162float(hn_hi));
            hpk_my[cbB * 512 + j0 + cjB] =
                (unsigned)__bfloat16_as_ushort(hn_hi)
                | ((unsigned)__bfloat16_as_ushort(hn_lo) << 16);
        }
        gbar16_arrive(mycnt);
        // deferred (non-peer-visible) stores overlap the barrier poll
        {
            size_t hrow = ((size_t)(b0 + cbB) * SEQ + t) * HDIM + j0 + cjB;
            g_Hh[hrow] = hn_hi;
            g_Hl[hrow] = hn_lo;
            if (t == SEQ - 1)
                out[(size_t)BATCH * SEQ * BDIM + (b0 + cbB) * HDIM + j0 + cjB] = hn;
        }
        gbar16_wait(mycnt, tgt); tgt += 16;
    }
}

// =====================================================================================
extern "C" void kernel_launch(void* const* d_in, const int* in_sizes, int n_in,
                              void* d_out, int out_size)
{
    (void)in_sizes; (void)n_in; (void)out_size;
    const float* x  = (const float*)d_in[0];
    const float* Wz = (const float*)d_in[1];
    const float* bz = (const float*)d_in[2];
    const float* Wr = (const float*)d_in[3];
    const float* br = (const float*)d_in[4];
    const float* Wh = (const float*)d_in[5];
    const float* bh = (const float*)d_in[6];
    const float* Wb = (const float*)d_in[7];
    const float* bb = (const float*)d_in[8];
    float* out = (float*)d_out;

    cudaFuncSetAttribute(recurrent_tc_kernel,
                         cudaFuncAttributeMaxDynamicSharedMemorySize, SMEM2_TOTAL);
    cudaFuncSetAttribute(gemm_mma_kernel,
                         cudaFuncAttributeMaxDynamicSharedMemorySize, GEMM_SMEM);

    __nv_bfloat16 *Xh, *Xl, *Wxh, *Wxl, *Hh, *Hl, *Wbh, *Wbl;
    float *XG, *bcat;
    unsigned* cntp;
    cudaGetSymbolAddress((void**)&Xh,  g_Xh);
    cudaGetSymbolAddress((void**)&Xl,  g_Xl);
    cudaGetSymbolAddress((void**)&Wxh, g_Wxh);
    cudaGetSymbolAddress((void**)&Wxl, g_Wxl);
    cudaGetSymbolAddress((void**)&Hh,  g_Hh);
    cudaGetSymbolAddress((void**)&Hl,  g_Hl);
    cudaGetSymbolAddress((void**)&Wbh, g_Wbh);
    cudaGetSymbolAddress((void**)&Wbl, g_Wbl);
    cudaGetSymbolAddress((void**)&XG,  g_XG);
    cudaGetSymbolAddress((void**)&bcat, g_bcat);
    cudaGetSymbolAddress((void**)&cntp, g_cnt8);

    // Prep: bf16 hi/lo splits
    prep_wx_kernel<<<(NG * XPART + 255) / 256, 256>>>(Wz, Wr, Wh, bz, br, bh);
    prep_wb_kernel<<<(BDIM * HDIM + 255) / 256, 256>>>(Wb);
    prep_x_kernel<<<(M_TOTAL * XPART / 4) / 256, 256>>>(x);

    // Stage 1: XG = xcat @ Wx^T + bcat  (24 super-chunks)
    gemm_mma_kernel<<<dim3(NG / 128, M_TOTAL / 128), 256, GEMM_SMEM>>>(
        Xh, Xl, XPART, Wxh, Wxl, XPART, bcat, XG, NG, XPART / 32);

    // Stage 2: persistent tensor-core recurrence (writes g_Hh/g_Hl + h_fin tail)
    cudaMemsetAsync(cntp, 0, 8 * 32 * sizeof(unsigned));
    recurrent_tc_kernel<<<NBLK2, 256, SMEM2_TOTAL>>>(Wz, Wr, Wh, out);

    // Stage 3: out = H @ Wb^T + bb  (16 super-chunks)
    gemm_mma_kernel<<<dim3(BDIM / 128, M_TOTAL / 128), 256, GEMM_SMEM>>>(
        Hh, Hl, HDIM, Wbh, Wbl, HDIM, bb, out, BDIM, HDIM / 32);
}

// round 17
// speedup vs baseline: 2.9971x; 1.0059x over previous
#include <cuda_runtime.h>
#include <cuda_bf16.h>
#include <cstdint>
#include <cstddef>

// Problem constants
#define BATCH   64
#define SEQ     2048
#define IDIM    256
#define HDIM    512
#define BDIM    256
#define INDIM   1280     // 3*IDIM + HDIM
#define XPART   768      // 3*IDIM
#define M_TOTAL (BATCH * SEQ)   // 131072
#define NG      1536     // 3 gates * HDIM

#define NBLK2   128      // persistent recurrent grid (1 CTA/SM -> co-resident)

// -------------------- scratch (static __device__, allocation-free) --------------------
__device__ float g_XG[(size_t)M_TOTAL * NG];        // [b*SEQ+t][1536]: xz | xr | xh pre-acts
__device__ unsigned g_cnt8[8 * 32];                 // per-batch-slab barrier counters (padded)

// packed bf16 hi|lo exchange buffers (u32 = hi | lo<<16)
__device__ unsigned g_hpk [BATCH * HDIM];           // h_t
__device__ unsigned g_rhpk[BATCH * HDIM];           // r*h

// bf16 split operands
__device__ __nv_bfloat16 g_Xh[(size_t)M_TOTAL * XPART];   // x concat hi, [b*SEQ+t][768]
__device__ __nv_bfloat16 g_Xl[(size_t)M_TOTAL * XPART];
__device__ __nv_bfloat16 g_Wxh[(size_t)NG * XPART];       // [1536][768] x-part of Wz|Wr|Wh
__device__ __nv_bfloat16 g_Wxl[(size_t)NG * XPART];
__device__ __nv_bfloat16 g_Hh[(size_t)M_TOTAL * HDIM];    // hidden states, [b*SEQ+t][512]
__device__ __nv_bfloat16 g_Hl[(size_t)M_TOTAL * HDIM];
__device__ __nv_bfloat16 g_Wbh[(size_t)BDIM * HDIM];
__device__ __nv_bfloat16 g_Wbl[(size_t)BDIM * HDIM];
__device__ float g_bcat[NG];

// =====================================================================================
// MMA / ldmatrix / cp.async macros (portable sm_80+ PTX)
// =====================================================================================
#define LDM_X4(r0, r1, r2, r3, a) \
    asm volatile("ldmatrix.sync.aligned.m8n8.x4.shared.b16 {%0,%1,%2,%3}, [%4];" \
                 : "=r"(r0), "=r"(r1), "=r"(r2), "=r"(r3) : "r"(a))
#define LDM_X2(r0, r1, a) \
    asm volatile("ldmatrix.sync.aligned.m8n8.x2.shared.b16 {%0,%1}, [%2];" \
                 : "=r"(r0), "=r"(r1) : "r"(a))
#define MMA16816(d, a, b) \
    asm volatile("mma.sync.aligned.m16n8k16.row.col.f32.bf16.bf16.f32 " \
                 "{%0,%1,%2,%3}, {%4,%5,%6,%7}, {%8,%9}, {%0,%1,%2,%3};" \
                 : "+f"((d)[0]), "+f"((d)[1]), "+f"((d)[2]), "+f"((d)[3]) \
                 : "r"((a)[0]), "r"((a)[1]), "r"((a)[2]), "r"((a)[3]), \
                   "r"((b)[0]), "r"((b)[1]))
#define CP_ASYNC16(dst, src) \
    asm volatile("cp.async.cg.shared.global [%0], [%1], 16;" :: "r"(dst), "l"(src))
#define CP_COMMIT() asm volatile("cp.async.commit_group;" ::: "memory")
#define CP_WAIT1()  asm volatile("cp.async.wait_group 1;" ::: "memory")
#define CP_WAIT0()  asm volatile("cp.async.wait_group 0;" ::: "memory")

__device__ __forceinline__ uint32_t smem_u32(const void* p) {
    uint32_t a;
    asm("{ .reg .u64 t; cvta.to.shared.u64 t, %1; cvt.u32.u64 %0, t; }" : "=r"(a) : "l"(p));
    return a;
}
// fast sigmoid: 0.5 + 0.5*tanh(0.5x)  (single MUFU)
__device__ __forceinline__ float sigmoid_fast(float x) {
    float th;
    asm("tanh.approx.f32 %0, %1;" : "=f"(th) : "f"(x * 0.5f));
    return fmaf(th, 0.5f, 0.5f);
}

// =====================================================================================
// Prep kernels: build bf16 hi/lo split operands
// =====================================================================================
__global__ void __launch_bounds__(256) prep_wx_kernel(
    const float* __restrict__ Wz, const float* __restrict__ Wr, const float* __restrict__ Wh,
    const float* __restrict__ bz, const float* __restrict__ br, const float* __restrict__ bh)
{
    int idx = blockIdx.x * 256 + threadIdx.x;
    if (idx < NG * XPART) {
        int j = idx / XPART, k = idx - j * XPART;
        int gate = j >> 9, jj = j & 511;
        const float* W = (gate == 0) ? Wz : (gate == 1) ? Wr : Wh;
        float v = W[(size_t)jj * INDIM + k];
        __nv_bfloat16 hi = __float2bfloat16(v);
        __nv_bfloat16 lo = __float2bfloat16(v - __bfloat162float(hi));
        g_Wxh[idx] = hi; g_Wxl[idx] = lo;
    }
    if (idx < NG) {
        g_bcat[idx] = (idx < 512) ? bz[idx] : (idx < 1024) ? br[idx - 512] : bh[idx - 1024];
    }
}

__global__ void __launch_bounds__(256) prep_wb_kernel(const float* __restrict__ Wb)
{
    int idx = blockIdx.x * 256 + threadIdx.x;
    if (idx < BDIM * HDIM) {
        float v = Wb[idx];
        __nv_bfloat16 hi = __float2bfloat16(v);
        __nv_bfloat16 lo = __float2bfloat16(v - __bfloat162float(hi));
        g_Wbh[idx] = hi; g_Wbl[idx] = lo;
    }
}

// x (b, s, t, i) -> Xh/Xl[(b*SEQ+t)*768 + s*256 + i]
__global__ void __launch_bounds__(256) prep_x_kernel(const float* __restrict__ x)
{
    int idx = blockIdx.x * 256 + threadIdx.x;      // one float4
    size_t e = (size_t)idx * 4;
    int b = (int)(e / 1572864);                    // 3*2048*256
    int r = (int)(e - (size_t)b * 1572864);
    int s = r / 524288;                            // 2048*256
    int r2 = r - s * 524288;
    int t = r2 >> 8, i = r2 & 255;
    float4 v = *(const float4*)(x + e);
    size_t dst = ((size_t)b * SEQ + t) * XPART + s * 256 + i;
    __nv_bfloat16 hx = __float2bfloat16(v.x), hy = __float2bfloat16(v.y);
    __nv_bfloat16 hz = __float2bfloat16(v.z), hw = __float2bfloat16(v.w);
    *(__nv_bfloat162*)(g_Xh + dst)     = __nv_bfloat162(hx, hy);
    *(__nv_bfloat162*)(g_Xh + dst + 2) = __nv_bfloat162(hz, hw);
    *(__nv_bfloat162*)(g_Xl + dst)     = __nv_bfloat162(
        __float2bfloat16(v.x - __bfloat162float(hx)), __float2bfloat16(v.y - __bfloat162float(hy)));
    *(__nv_bfloat162*)(g_Xl + dst + 2) = __nv_bfloat162(
        __float2bfloat16(v.z - __bfloat162float(hz)), __float2bfloat16(v.w - __bfloat162float(hw)));
}

// =====================================================================================
// cp.async double-buffered SUPER-CHUNK mma.sync GEMM (stages 1 & 3) — round-10 version.
// =====================================================================================
#define GSTRIDE 80                      // smem row stride bytes (32 bf16 data + 8 pad)
#define G_TILE  (128 * GSTRIDE)         // 10240
#define G_STAGE (4 * G_TILE)            // 40960: Ah | Al | Bh | Bl
#define GEMM_SMEM (2 * G_STAGE)         // 81920

__global__ void __launch_bounds__(256, 2) gemm_mma_kernel(
    const __nv_bfloat16* __restrict__ Ah, const __nv_bfloat16* __restrict__ Al, int lda,
    const __nv_bfloat16* __restrict__ Bh, const __nv_bfloat16* __restrict__ Bl, int ldb,
    const float* __restrict__ bias, float* __restrict__ C, int ldc, int K32)
{
    extern __shared__ char gsm[];
    const uint32_t sbase = smem_u32(gsm);

    const int tid  = threadIdx.x;
    const int wid  = tid >> 5;
    const int lane = tid & 31;
    const int n0   = blockIdx.x * 128;
    const int m0   = blockIdx.y * 128;
    const int m0w  = (wid & 1) * 64;
    const int n0w  = (wid >> 1) * 32;

    const int NC = K32;                 // super-chunks

    const uint32_t a_base = (uint32_t)(((lane & 7) + ((lane >> 3) & 1) * 8) * GSTRIDE
                                       + ((lane >> 4) & 1) * 16);
    const uint32_t b_base = (uint32_t)(((lane & 7) + ((lane >> 4) & 1) * 8) * GSTRIDE
                                       + ((lane >> 3) & 1) * 16);

    float acc[4][4][4];
    #pragma unroll
    for (int i = 0; i < 4; i++)
        #pragma unroll
        for (int j = 0; j < 4; j++)
            #pragma unroll
            for (int q = 0; q < 4; q++) acc[i][j][q] = 0.f;

    auto issue = [&](int c) {
        const int kk = c * 32;
        const uint32_t sb = sbase + (uint32_t)((c & 1) * G_STAGE);
        const int u = tid, row = u >> 2, c16 = u & 3;
        #pragma unroll
        for (int i = 0; i < 2; i++) {
            int rr = row + i * 64;
            uint32_t so = (uint32_t)(rr * GSTRIDE + c16 * 16);
            size_t goA = (size_t)(m0 + rr) * lda + kk + c16 * 8;
            size_t goB = (size_t)(n0 + rr) * ldb + kk + c16 * 8;
            CP_ASYNC16(sb + so,              Ah + goA);
            CP_ASYNC16(sb + G_TILE + so,     Al + goA);
            CP_ASYNC16(sb + 2*G_TILE + so,   Bh + goB);
            CP_ASYNC16(sb + 3*G_TILE + so,   Bl + goB);
        }
        CP_COMMIT();
    };

    issue(0);

    #pragma unroll 1
    for (int c = 0; c < NC; c++) {
        if (c + 1 < NC) { issue(c + 1); CP_WAIT1(); } else { CP_WAIT0(); }
        __syncthreads();

        const uint32_t sb  = sbase + (uint32_t)((c & 1) * G_STAGE);
        const uint32_t sAh = sb + (uint32_t)(m0w * GSTRIDE) + a_base;
        const uint32_t sAl = sAh + G_TILE;
        const uint32_t sBh = sb + 2*G_TILE + (uint32_t)(n0w * GSTRIDE) + b_base;
        const uint32_t sBl = sBh + G_TILE;

        #pragma unroll
        for (int ks = 0; ks < 2; ks++) {
            const uint32_t ko = (uint32_t)(ks * 32);
            uint32_t ahf[4][4], bhf[4][2];
            #pragma unroll
            for (int mb = 0; mb < 4; mb++)
                LDM_X4(ahf[mb][0], ahf[mb][1], ahf[mb][2], ahf[mb][3],
                       sAh + (uint32_t)(mb * 16 * GSTRIDE) + ko);
            #pragma unroll
            for (int q = 0; q < 2; q++)
                LDM_X4(bhf[2*q][0], bhf[2*q][1], bhf[2*q+1][0], bhf[2*q+1][1],
                       sBh + (uint32_t)(q * 16 * GSTRIDE) + ko);
            #pragma unroll
            for (int mb = 0; mb < 4; mb++)
                #pragma unroll
                for (int nb = 0; nb < 4; nb++)
                    MMA16816(acc[mb][nb], ahf[mb], bhf[nb]);     // Ah*Bh

            uint32_t alf[4][4];
            #pragma unroll
            for (int mb = 0; mb < 4; mb++)
                LDM_X4(alf[mb][0], alf[mb][1], alf[mb][2], alf[mb][3],
                       sAl + (uint32_t)(mb * 16 * GSTRIDE) + ko);
            #pragma unroll
            for (int mb = 0; mb < 4; mb++)
                #pragma unroll
                for (int nb = 0; nb < 4; nb++)
                    MMA16816(acc[mb][nb], alf[mb], bhf[nb]);     // Al*Bh

            uint32_t blf[4][2];
            #pragma unroll
            for (int q = 0; q < 2; q++)
                LDM_X4(blf[2*q][0], blf[2*q][1], blf[2*q+1][0], blf[2*q+1][1],
                       sBl + (uint32_t)(q * 16 * GSTRIDE) + ko);
            #pragma unroll
            for (int mb = 0; mb < 4; mb++)
                #pragma unroll
                for (int nb = 0; nb < 4; nb++)
                    MMA16816(acc[mb][nb], ahf[mb], blf[nb]);     // Ah*Bl
        }
        __syncthreads();
    }

    const int g   = lane >> 2;
    const int tig = lane & 3;
    #pragma unroll
    for (int mb = 0; mb < 4; mb++) {
        #pragma unroll
        for (int nb = 0; nb < 4; nb++) {
            int col = n0 + n0w + nb * 8 + tig * 2;
            float b0 = bias[col], b1 = bias[col + 1];
            int r0 = m0 + m0w + mb * 16 + g;
            *(float2*)(C + (size_t)r0 * ldc + col) =
                make_float2(acc[mb][nb][0] + b0, acc[mb][nb][1] + b1);
            *(float2*)(C + (size_t)(r0 + 8) * ldc + col) =
                make_float2(acc[mb][nb][2] + b0, acc[mb][nb][3] + b1);
        }
    }
}

// =====================================================================================
// Stage 2: persistent TENSOR-CORE recurrence — round-15 structure plus:
//   (1) combine-A sigmoid via tanh.approx (one MUFU on the serial chain)
//   (2) streaming cache hints: XG loads ld.global.cs, H-history stores st.global.cs
// =====================================================================================
#define WROW   1040                 // weight/A smem row stride in bytes (520 bf16)
#define OFF_WZRH 0
#define OFF_WZRL (OFF_WZRH + 64*WROW)
#define OFF_WHH  (OFF_WZRL + 64*WROW)
#define OFF_WHL  (OFF_WHH  + 32*WROW)
#define OFF_AHI  (OFF_WHL  + 32*WROW)
#define OFF_ALO  (OFF_AHI  + 8*WROW)
#define OFF_CRED (OFF_ALO  + 8*WROW)
#define OFF_H32  (OFF_CRED + 2*8*66*4)
#define OFF_ZB   (OFF_H32  + 1024)
#define SMEM2_TOTAL (OFF_ZB + 1024)

#define CRED(p, h, r, n) p[((h) * 8 + (r)) * 66 + (n)]

// per-slab barrier: 16 arrivals, monotonic counter (round-8/10 proven primitive)
__device__ __forceinline__ void gbar16(unsigned* cnt, unsigned target) {
    __syncthreads();
    if (threadIdx.x == 0) {
        asm volatile("red.release.gpu.global.add.u32 [%0], %1;" :: "l"(cnt), "r"(1u));
        unsigned c;
        do {
            asm volatile("ld.acquire.gpu.global.u32 %0, [%1];" : "=r"(c) : "l"(cnt));
        } while ((int)(c - target) < 0);
    }
    __syncthreads();
}
__device__ __forceinline__ void gbar16_arrive(unsigned* cnt) {
    __syncthreads();
    if (threadIdx.x == 0)
        asm volatile("red.release.gpu.global.add.u32 [%0], %1;" :: "l"(cnt), "r"(1u));
}
__device__ __forceinline__ void gbar16_wait(unsigned* cnt, unsigned target) {
    if (threadIdx.x == 0) {
        unsigned c;
        do {
            asm volatile("ld.acquire.gpu.global.u32 %0, [%1];" : "=r"(c) : "l"(cnt));
        } while ((int)(c - target) < 0);
    }
    __syncthreads();
}

__global__ void __launch_bounds__(256, 1) recurrent_tc_kernel(
    const float* __restrict__ Wz, const float* __restrict__ Wr, const float* __restrict__ Wh,
    float* __restrict__ out)
{
    extern __shared__ char smem[];
    const uint32_t sbase = smem_u32(smem);
    float* credf = (float*)(smem + OFF_CRED);
    float* h32   = (float*)(smem + OFF_H32);
    float* zbuf  = (float*)(smem + OFF_ZB);

    const int tid  = threadIdx.x;
    const int wid  = tid >> 5;
    const int lane = tid & 31;
    const int blk  = blockIdx.x;
    const int bslab = blk >> 4;
    const int b0   = bslab * 8;
    const int j0   = (blk & 15) * 32;
    unsigned* mycnt = &g_cnt8[bslab * 32];

    // ---- load + split weights into smem (one-time) ----
    for (int e = tid; e < 64 * 512; e += 256) {
        int row = e >> 9, k = e & 511;
        const float* W = (row < 32) ? Wz : Wr;
        float v = W[(size_t)(j0 + (row & 31)) * INDIM + XPART + k];
        __nv_bfloat16 hi = __float2bfloat16(v);
        __nv_bfloat16 lo = __float2bfloat16(v - __bfloat162float(hi));
        *(__nv_bfloat16*)(smem + OFF_WZRH + row * WROW + k * 2) = hi;
        *(__nv_bfloat16*)(smem + OFF_WZRL + row * WROW + k * 2) = lo;
    }
    for (int e = tid; e < 32 * 512; e += 256) {
        int row = e >> 9, k = e & 511;
        float v = Wh[(size_t)(j0 + row) * INDIM + XPART + k];
        __nv_bfloat16 hi = __float2bfloat16(v);
        __nv_bfloat16 lo = __float2bfloat16(v - __bfloat162float(hi));
        *(__nv_bfloat16*)(smem + OFF_WHH + row * WROW + k * 2) = hi;
        *(__nv_bfloat16*)(smem + OFF_WHL + row * WROW + k * 2) = lo;
    }
    h32[tid] = 0.f;
    g_hpk[(b0 + (tid >> 5)) * HDIM + j0 + (tid & 31)] = 0u;

    unsigned tgt = 16;
    gbar16(mycnt, tgt); tgt += 16;

    // ---- per-warp fragment address bases ----
    const int kh  = wid >> 2;                // K half: 0 -> k[0,256), 1 -> k[256,512)
    const int khB = kh * 512;                // byte offset of K half
    const int arow  = lane & 7;
    const int isLo  = (lane >> 3) & 1;       // lanes 8-15 / 24-31 -> lo rows
    const uint32_t akof = (uint32_t)(((lane >> 4) & 1) * 16);
    const uint32_t aA = sbase + (isLo ? OFF_ALO : OFF_AHI) + arow * WROW + akof + khB;

    const int nsA = wid & 3;                 // phase A N16 slice
    const int browA = nsA * 16 + (lane & 7) + ((lane >> 4) & 1) * 8;
    const uint32_t bkofA = (uint32_t)(((lane >> 3) & 1) * 16);
    const uint32_t bZH = sbase + OFF_WZRH + browA * WROW + bkofA + khB;
    const uint32_t bZL = sbase + OFF_WZRL + browA * WROW + bkofA + khB;

    const int browB = (wid & 3) * 8 + (lane & 7);   // phase B N8 slice
    const uint32_t bkofB = (uint32_t)(((lane >> 3) & 1) * 16);
    const uint32_t bWH = sbase + OFF_WHH + browB * WROW + bkofB + khB;
    const uint32_t bWL = sbase + OFF_WHL + browB * WROW + bkofB + khB;

    // combine mappings + running XG pointers
    const int cbA = tid >> 6;                // combine A: batches cbA and cbA+4
    const int cnA = tid & 63;                // 0..31 -> z, 32..63 -> r
    const int colA = (cnA < 32) ? (j0 + cnA) : (512 + j0 + (cnA - 32));
    const float* pxA0 = g_XG + (size_t)(b0 + cbA)     * SEQ * NG + colA;
    const float* pxA1 = g_XG + (size_t)(b0 + cbA + 4) * SEQ * NG + colA;
    const int cbB = tid >> 5, cjB = tid & 31;
    const float* pxB = g_XG + (size_t)(b0 + cbB) * SEQ * NG + 1024 + j0 + cjB;

    const int crow = lane >> 2;              // C frag row (0..7)
    const int ccol = (lane & 3) * 2;

    unsigned* hpk_my  = g_hpk  + (size_t)b0 * HDIM;
    unsigned* rhpk_my = g_rhpk + (size_t)b0 * HDIM;

    #pragma unroll 1
    for (int t = 0; t < SEQ; t++) {
        // prefetch XG for this step (streaming: read once)
        float xa0 = __ldcs(pxA0), xa1 = __ldcs(pxA1), xb = __ldcs(pxB);
        pxA0 += NG; pxA1 += NG; pxB += NG;

        // ---- load h (packed) -> Ahi/Alo ----
        #pragma unroll
        for (int q = 0; q < 8; q++) {
            uint2 w = *(const uint2*)(hpk_my + q * 512 + tid * 2);
            *(uint32_t*)(smem + OFF_AHI + q * WROW + tid * 4) = __byte_perm(w.x, w.y, 0x5410);
            *(uint32_t*)(smem + OFF_ALO + q * WROW + tid * 4) = __byte_perm(w.x, w.y, 0x7632);
        }
        __syncthreads();

        // ---- phase A mma: z|r preacts, N64; 4-way split accumulators ----
        {
            float a0h[2][4], a0l[2][4], a1h[2][4], a1l[2][4];
            #pragma unroll
            for (int p = 0; p < 2; p++)
                #pragma unroll
                for (int q = 0; q < 4; q++) {
                    a0h[p][q] = 0.f; a0l[p][q] = 0.f;
                    a1h[p][q] = 0.f; a1l[p][q] = 0.f;
                }
            #pragma unroll
            for (int k16 = 0; k16 < 16; k16++) {
                const int p = k16 & 1;
                uint32_t off = (uint32_t)(k16 * 32);
                uint32_t a[4], bh[4], bl[4];
                LDM_X4(a[0], a[1], a[2], a[3], aA + off);
                LDM_X4(bh[0], bh[1], bh[2], bh[3], bZH + off);
                LDM_X4(bl[0], bl[1], bl[2], bl[3], bZL + off);
                MMA16816(a0h[p], a, bh);
                MMA16816(a1h[p], a, bh + 2);
                MMA16816(a0l[p], a, bl);
                MMA16816(a1l[p], a, bl + 2);
            }
            int n0w = nsA * 16;
            float s00 = a0h[0][0] + a0h[1][0] + a0l[0][0] + a0l[1][0]
                      + a0h[0][2] + a0h[1][2] + a0l[0][2] + a0l[1][2];
            float s01 = a0h[0][1] + a0h[1][1] + a0l[0][1] + a0l[1][1]
                      + a0h[0][3] + a0h[1][3] + a0l[0][3] + a0l[1][3];
            float s10 = a1h[0][0] + a1h[1][0] + a1l[0][0] + a1l[1][0]
                      + a1h[0][2] + a1h[1][2] + a1l[0][2] + a1l[1][2];
            float s11 = a1h[0][1] + a1h[1][1] + a1l[0][1] + a1l[1][1]
                      + a1h[0][3] + a1h[1][3] + a1l[0][3] + a1l[1][3];
            *(float2*)&CRED(credf, kh, crow, n0w + ccol)     = make_float2(s00, s01);
            *(float2*)&CRED(credf, kh, crow, n0w + 8 + ccol) = make_float2(s10, s11);
        }
        __syncthreads();

        // ---- combine A: fast sigmoid, publish z (smem) and r*h (global packed) ----
        {
            #pragma unroll
            for (int it = 0; it < 2; it++) {
                int b = cbA + it * 4;
                float s = CRED(credf, 0, b, cnA) + CRED(credf, 1, b, cnA)
                        + (it == 0 ? xa0 : xa1);
                float sig = sigmoid_fast(s);
                if (cnA < 32) {
                    zbuf[b * 32 + cnA] = sig;
                } else {
                    int jl = cnA - 32;
                    float rh = sig * h32[b * 32 + jl];
                    __nv_bfloat16 hi = __float2bfloat16(rh);
                    __nv_bfloat16 lo = __float2bfloat16(rh - __bfloat162float(hi));
                    rhpk_my[b * 512 + j0 + jl] =
                        (unsigned)__bfloat16_as_ushort(hi)
                        | ((unsigned)__bfloat16_as_ushort(lo) << 16);
                }
            }
        }
        gbar16(mycnt, tgt); tgt += 16;

        // ---- load rh (packed) -> Ahi/Alo ----
        #pragma unroll
        for (int q = 0; q < 8; q++) {
            uint2 w = *(const uint2*)(rhpk_my + q * 512 + tid * 2);
            *(uint32_t*)(smem + OFF_AHI + q * WROW + tid * 4) = __byte_perm(w.x, w.y, 0x5410);
            *(uint32_t*)(smem + OFF_ALO + q * WROW + tid * 4) = __byte_perm(w.x, w.y, 0x7632);
        }
        __syncthreads();

        // ---- phase B mma: h~ preacts, N32; 4-way split accumulators ----
        {
            float ah[2][4], al[2][4];
            #pragma unroll
            for (int p = 0; p < 2; p++)
                #pragma unroll
                for (int q = 0; q < 4; q++) { ah[p][q] = 0.f; al[p][q] = 0.f; }
            #pragma unroll
            for (int k16 = 0; k16 < 16; k16++) {
                const int p = k16 & 1;
                uint32_t off = (uint32_t)(k16 * 32);
                uint32_t a[4], bh[2], bl[2];
                LDM_X4(a[0], a[1], a[2], a[3], aA + off);
                LDM_X2(bh[0], bh[1], bWH + off);
                LDM_X2(bl[0], bl[1], bWL + off);
                MMA16816(ah[p], a, bh);
                MMA16816(al[p], a, bl);
            }
            int n0w = (wid & 3) * 8;
            float s0 = ah[0][0] + ah[1][0] + al[0][0] + al[1][0]
                     + ah[0][2] + ah[1][2] + al[0][2] + al[1][2];
            float s1 = ah[0][1] + ah[1][1] + al[0][1] + al[1][1]
                     + ah[0][3] + ah[1][3] + al[0][3] + al[1][3];
            *(float2*)&CRED(credf, kh, crow, n0w + ccol) = make_float2(s0, s1);
        }
        __syncthreads();

        // ---- combine B: tanh.approx, blend, publish h (peer-visible first) ----
        float hn;
        __nv_bfloat16 hn_hi, hn_lo;
        {
            float s = CRED(credf, 0, cbB, cjB) + CRED(credf, 1, cbB, cjB) + xb;
            float ht;
            asm("tanh.approx.f32 %0, %1;" : "=f"(ht) : "f"(s));
            float hp = h32[tid];
            float z  = zbuf[tid];
            hn = hp + z * (ht - hp);
            h32[tid] = hn;
            hn_hi = __float2bfloat16(hn);
            hn_lo = __float2bfloat16(hn - __bfloat162float(hn_hi));
            hpk_my[cbB * 512 + j0 + cjB] =
                (unsigned)__bfloat16_as_ushort(hn_hi)
                | ((unsigned)__bfloat16_as_ushort(hn_lo) << 16);
        }
        gbar16_arrive(mycnt);
        // deferred (non-peer-visible) stores overlap the barrier poll; streaming hint
        {
            size_t hrow = ((size_t)(b0 + cbB) * SEQ + t) * HDIM + j0 + cjB;
            asm volatile("st.global.cs.u16 [%0], %1;"
                         :: "l"(g_Hh + hrow), "h"(__bfloat16_as_ushort(hn_hi)));
            asm volatile("st.global.cs.u16 [%0], %1;"
                         :: "l"(g_Hl + hrow), "h"(__bfloat16_as_ushort(hn_lo)));
            if (t == SEQ - 1)
                out[(size_t)BATCH * SEQ * BDIM + (b0 + cbB) * HDIM + j0 + cjB] = hn;
        }
        gbar16_wait(mycnt, tgt); tgt += 16;
    }
}

// =====================================================================================
extern "C" void kernel_launch(void* const* d_in, const int* in_sizes, int n_in,
                              void* d_out, int out_size)
{
    (void)in_sizes; (void)n_in; (void)out_size;
    const float* x  = (const float*)d_in[0];
    const float* Wz = (const float*)d_in[1];
    const float* bz = (const float*)d_in[2];
    const float* Wr = (const float*)d_in[3];
    const float* br = (const float*)d_in[4];
    const float* Wh = (const float*)d_in[5];
    const float* bh = (const float*)d_in[6];
    const float* Wb = (const float*)d_in[7];
    const float* bb = (const float*)d_in[8];
    float* out = (float*)d_out;

    cudaFuncSetAttribute(recurrent_tc_kernel,
                         cudaFuncAttributeMaxDynamicSharedMemorySize, SMEM2_TOTAL);
    cudaFuncSetAttribute(gemm_mma_kernel,
                         cudaFuncAttributeMaxDynamicSharedMemorySize, GEMM_SMEM);

    __nv_bfloat16 *Xh, *Xl, *Wxh, *Wxl, *Hh, *Hl, *Wbh, *Wbl;
    float *XG, *bcat;
    unsigned* cntp;
    cudaGetSymbolAddress((void**)&Xh,  g_Xh);
    cudaGetSymbolAddress((void**)&Xl,  g_Xl);
    cudaGetSymbolAddress((void**)&Wxh, g_Wxh);
    cudaGetSymbolAddress((void**)&Wxl, g_Wxl);
    cudaGetSymbolAddress((void**)&Hh,  g_Hh);
    cudaGetSymbolAddress((void**)&Hl,  g_Hl);
    cudaGetSymbolAddress((void**)&Wbh, g_Wbh);
    cudaGetSymbolAddress((void**)&Wbl, g_Wbl);
    cudaGetSymbolAddress((void**)&XG,  g_XG);
    cudaGetSymbolAddress((void**)&bcat, g_bcat);
    cudaGetSymbolAddress((void**)&cntp, g_cnt8);

    // Prep: bf16 hi/lo splits
    prep_wx_kernel<<<(NG * XPART + 255) / 256, 256>>>(Wz, Wr, Wh, bz, br, bh);
    prep_wb_kernel<<<(BDIM * HDIM + 255) / 256, 256>>>(Wb);
    prep_x_kernel<<<(M_TOTAL * XPART / 4) / 256, 256>>>(x);

    // Stage 1: XG = xcat @ Wx^T + bcat  (24 super-chunks)
    gemm_mma_kernel<<<dim3(NG / 128, M_TOTAL / 128), 256, GEMM_SMEM>>>(
        Xh, Xl, XPART, Wxh, Wxl, XPART, bcat, XG, NG, XPART / 32);

    // Stage 2: persistent tensor-core recurrence (writes g_Hh/g_Hl + h_fin tail)
    cudaMemsetAsync(cntp, 0, 8 * 32 * sizeof(unsigned));
    recurrent_tc_kernel<<<NBLK2, 256, SMEM2_TOTAL>>>(Wz, Wr, Wh, out);

    // Stage 3: out = H @ Wb^T + bb  (16 super-chunks)
    gemm_mma_kernel<<<dim3(BDIM / 128, M_TOTAL / 128), 256, GEMM_SMEM>>>(
        Hh, Hl, HDIM, Wbh, Wbl, HDIM, bb, out, BDIM, HDIM / 32);
}